// round 2
// baseline (speedup 1.0000x reference)
#include <cuda_runtime.h>
#include <math.h>

// Problem constants
#define B_   4
#define H_   8
#define N_   8192
#define D_   512
#define DH_  64
#define M_   256
#define L_   32
#define BH_  32            // B_*H_
#define IN3_ 1536          // 3*H_*DH_

// ---------------- scratch (device globals; no allocation anywhere) ----------------
__device__ float gQ[16777216];     // [BH,N,DH] (pre-scaled by dh^-0.5)
__device__ float gK[16777216];
__device__ float gV[16777216];
__device__ float gQL[524288];      // [BH,M,DH]
__device__ float gKL[524288];
__device__ float gA2[2097152];     // [BH,M,M] softmaxed
__device__ float gZ [2097152];
__device__ float gZ2[2097152];
__device__ float gX [2097152];
__device__ float gU1[2097152];
__device__ float gU2[2097152];
__device__ float gA3V[524288];     // [BH,M,DH]
__device__ float gW [524288];      // [BH,M,DH]
__device__ float gOH[16777216];    // [BH,N,DH]
__device__ float gCAT[16777216];   // [B,N,512]
__device__ int   gMaxBits;

// ---------------- generic NN GEMM: C = s*(A@B) + dI*I (+bias), 128x128x8, 8x8/thread ------
__global__ __launch_bounds__(256) void gemm_nn(
    const float* __restrict__ A, const float* __restrict__ B,
    float* __restrict__ C, const float* __restrict__ bias,
    int Md, int Nd, int Kd,
    long long sA, long long sB, long long sC,
    float s, float dI)
{
    A += (long long)blockIdx.z * sA;
    B += (long long)blockIdx.z * sB;
    C += (long long)blockIdx.z * sC;
    const int m0 = blockIdx.x * 128;
    const int n0 = blockIdx.y * 128;
    const int tid = threadIdx.x;
    const int tx = tid & 15, ty = tid >> 4;

    __shared__ float As[8][132];
    __shared__ float Bs[8][128];

    float acc[8][8];
#pragma unroll
    for (int i = 0; i < 8; i++)
#pragma unroll
        for (int j = 0; j < 8; j++) acc[i][j] = 0.f;

    const int ar = tid >> 1;
    const int ac = (tid & 1) * 4;
    const int bk = tid >> 5;
    const int bn = (tid & 31) * 4;
    const int arow = m0 + ar;
    const int bcol = n0 + bn;
    const bool aok = (arow < Md);
    const bool bok = (bcol < Nd);

    for (int kk = 0; kk < Kd; kk += 8) {
        float4 av = make_float4(0.f, 0.f, 0.f, 0.f);
        if (aok) av = *(const float4*)(A + (long long)arow * Kd + (kk + ac));
        float4 bv = make_float4(0.f, 0.f, 0.f, 0.f);
        if (bok) bv = *(const float4*)(B + (long long)(kk + bk) * Nd + bcol);
        As[ac + 0][ar] = av.x; As[ac + 1][ar] = av.y;
        As[ac + 2][ar] = av.z; As[ac + 3][ar] = av.w;
        *(float4*)&Bs[bk][bn] = bv;
        __syncthreads();
#pragma unroll
        for (int k = 0; k < 8; k++) {
            float a[8], b[8];
            *(float4*)&a[0] = *(const float4*)&As[k][ty * 8];
            *(float4*)&a[4] = *(const float4*)&As[k][ty * 8 + 4];
            *(float4*)&b[0] = *(const float4*)&Bs[k][tx * 8];
            *(float4*)&b[4] = *(const float4*)&Bs[k][tx * 8 + 4];
#pragma unroll
            for (int i = 0; i < 8; i++)
#pragma unroll
                for (int j = 0; j < 8; j++)
                    acc[i][j] = fmaf(a[i], b[j], acc[i][j]);
        }
        __syncthreads();
    }
    const bool hasBias = (bias != nullptr);
#pragma unroll
    for (int i = 0; i < 8; i++) {
        int row = m0 + ty * 8 + i;
        if (row >= Md) continue;
#pragma unroll
        for (int jg = 0; jg < 8; jg += 4) {
            int col = n0 + tx * 8 + jg;
            if (col >= Nd) continue;
            float4 o;
            float* po = (float*)&o;
#pragma unroll
            for (int u = 0; u < 4; u++) {
                float v = s * acc[i][jg + u];
                if (dI != 0.f && row == col + u) v += dI;
                if (hasBias) v += bias[col + u];
                po[u] = v;
            }
            *(float4*)(C + (long long)row * Nd + col) = o;
        }
    }
}

// ---------------- qkv GEMM with scatter epilogue: x[32768,512] @ wqkv[512,1536] ----------
// Column c: which = c>>9, h = (c>>6)&7, d = c&63. Row r: b = r>>13, n = r&8191.
// Writes Q (scaled 0.125), K, V each as [BH,N,64].
__global__ __launch_bounds__(256) void gemm_qkv(
    const float* __restrict__ A, const float* __restrict__ B,
    float* __restrict__ Q, float* __restrict__ K, float* __restrict__ V)
{
    const int m0 = blockIdx.x * 128;
    const int n0 = blockIdx.y * 128;
    const int tid = threadIdx.x;
    const int tx = tid & 15, ty = tid >> 4;

    __shared__ float As[8][132];
    __shared__ float Bs[8][128];

    float acc[8][8];
#pragma unroll
    for (int i = 0; i < 8; i++)
#pragma unroll
        for (int j = 0; j < 8; j++) acc[i][j] = 0.f;

    const int ar = tid >> 1;
    const int ac = (tid & 1) * 4;
    const int bk = tid >> 5;
    const int bn = (tid & 31) * 4;
    const float* pA = A + (long long)(m0 + ar) * 512 + ac;
    const float* pB = B + (long long)bk * 1536 + (n0 + bn);

    for (int kk = 0; kk < 512; kk += 8) {
        float4 av = *(const float4*)(pA + kk);
        float4 bv = *(const float4*)(pB + (long long)kk * 1536);
        As[ac + 0][ar] = av.x; As[ac + 1][ar] = av.y;
        As[ac + 2][ar] = av.z; As[ac + 3][ar] = av.w;
        *(float4*)&Bs[bk][bn] = bv;
        __syncthreads();
#pragma unroll
        for (int k = 0; k < 8; k++) {
            float a[8], b[8];
            *(float4*)&a[0] = *(const float4*)&As[k][ty * 8];
            *(float4*)&a[4] = *(const float4*)&As[k][ty * 8 + 4];
            *(float4*)&b[0] = *(const float4*)&Bs[k][tx * 8];
            *(float4*)&b[4] = *(const float4*)&Bs[k][tx * 8 + 4];
#pragma unroll
            for (int i = 0; i < 8; i++)
#pragma unroll
                for (int j = 0; j < 8; j++)
                    acc[i][j] = fmaf(a[i], b[j], acc[i][j]);
        }
        __syncthreads();
    }
#pragma unroll
    for (int i = 0; i < 8; i++) {
        int row = m0 + ty * 8 + i;
        int b = row >> 13, n = row & (N_ - 1);
#pragma unroll
        for (int jg = 0; jg < 8; jg += 4) {
            int col = n0 + tx * 8 + jg;
            int which = col >> 9;
            int rem = col & 511;
            int h = rem >> 6, d = rem & 63;
            float4 o = make_float4(acc[i][jg], acc[i][jg + 1], acc[i][jg + 2], acc[i][jg + 3]);
            float* dst;
            if (which == 0) {
                o.x *= 0.125f; o.y *= 0.125f; o.z *= 0.125f; o.w *= 0.125f;
                dst = Q;
            } else dst = (which == 1) ? K : V;
            long long off = ((((long long)(b * H_ + h)) << 13) + n) * 64 + d;
            *(float4*)(dst + off) = o;
        }
    }
}

// ---------------- NT GEMM, inner dim 64 (attn2 scores) ----------------
__global__ __launch_bounds__(256) void gemm_nt64(
    const float* __restrict__ A, const float* __restrict__ B,
    float* __restrict__ C, int ldc,
    long long sA, long long sB, long long sC)
{
    A += (long long)blockIdx.z * sA;
    B += (long long)blockIdx.z * sB;
    C += (long long)blockIdx.z * sC;
    const int m0 = blockIdx.x * 128;
    const int n0 = blockIdx.y * 128;
    const int tid = threadIdx.x;
    const int tx = tid & 15, ty = tid >> 4;

    __shared__ float As[8][132];
    __shared__ float Bs[8][132];

    float acc[8][8];
#pragma unroll
    for (int i = 0; i < 8; i++)
#pragma unroll
        for (int j = 0; j < 8; j++) acc[i][j] = 0.f;

    const int r = tid >> 1;
    const int c = (tid & 1) * 4;
    const float* pA = A + (long long)(m0 + r) * 64 + c;
    const float* pB = B + (long long)(n0 + r) * 64 + c;

#pragma unroll
    for (int kk = 0; kk < 64; kk += 8) {
        float4 av = *(const float4*)(pA + kk);
        float4 bv = *(const float4*)(pB + kk);
        As[c + 0][r] = av.x; As[c + 1][r] = av.y; As[c + 2][r] = av.z; As[c + 3][r] = av.w;
        Bs[c + 0][r] = bv.x; Bs[c + 1][r] = bv.y; Bs[c + 2][r] = bv.z; Bs[c + 3][r] = bv.w;
        __syncthreads();
#pragma unroll
        for (int k = 0; k < 8; k++) {
            float a[8], b[8];
            *(float4*)&a[0] = *(const float4*)&As[k][ty * 8];
            *(float4*)&a[4] = *(const float4*)&As[k][ty * 8 + 4];
            *(float4*)&b[0] = *(const float4*)&Bs[k][tx * 8];
            *(float4*)&b[4] = *(const float4*)&Bs[k][tx * 8 + 4];
#pragma unroll
            for (int i = 0; i < 8; i++)
#pragma unroll
                for (int j = 0; j < 8; j++)
                    acc[i][j] = fmaf(a[i], b[j], acc[i][j]);
        }
        __syncthreads();
    }
#pragma unroll
    for (int i = 0; i < 8; i++) {
        int row = m0 + ty * 8 + i;
#pragma unroll
        for (int jg = 0; jg < 8; jg += 4) {
            int col = n0 + tx * 8 + jg;
            float4 o = make_float4(acc[i][jg], acc[i][jg + 1], acc[i][jg + 2], acc[i][jg + 3]);
            *(float4*)(C + (long long)row * ldc + col) = o;
        }
    }
}

// ---------------- fused online-softmax attention: Out = softmax(A @ B^T) @ V ----------
// A: [bh][rows][64] row tile of 64; B,V: [bh][nChunks*32][64]; Out: [bh][rows][64].
// Thread layout: r = tid>>2 (0..63 rows), cg = tid&3 (col/dim group).
__global__ __launch_bounds__(256) void fused_attn(
    const float* __restrict__ Arows, const float* __restrict__ Bmat,
    const float* __restrict__ Vmat, float* __restrict__ Out,
    int nChunks, long long sA, long long sB, long long sO)
{
    const int bh = blockIdx.y;
    const int row0 = blockIdx.x * 64;
    const float* Ab = Arows + (long long)bh * sA + (long long)row0 * 64;
    const float* Bb = Bmat + (long long)bh * sB;
    const float* Vb = Vmat + (long long)bh * sB;
    float* Ob = Out + (long long)bh * sO + (long long)row0 * 64;

    __shared__ float As[64][68];
    __shared__ float Kc[32][68];
    __shared__ float Vc[32][68];
    __shared__ float P[64][36];

    const int tid = threadIdx.x;
    const int r = tid >> 2;
    const int cg = tid & 3;

    // load A tile (64x64)
#pragma unroll
    for (int k = 0; k < 4; k++) {
        int f = tid + k * 256;
        int rr = f >> 4, c4 = (f & 15) * 4;
        *(float4*)&As[rr][c4] = *(const float4*)(Ab + (long long)rr * 64 + c4);
    }

    float acc[16];
#pragma unroll
    for (int i = 0; i < 16; i++) acc[i] = 0.f;
    float mrun = -3.0e38f, srun = 0.f;

    for (int ch = 0; ch < nChunks; ch++) {
        const float* Kg = Bb + (long long)ch * 32 * 64;
        const float* Vg = Vb + (long long)ch * 32 * 64;
#pragma unroll
        for (int k = 0; k < 2; k++) {
            int f = tid + k * 256;
            int jj = f >> 4, c4 = (f & 15) * 4;
            *(float4*)&Kc[jj][c4] = *(const float4*)(Kg + jj * 64 + c4);
            *(float4*)&Vc[jj][c4] = *(const float4*)(Vg + jj * 64 + c4);
        }
        __syncthreads();

        // scores: 8 per thread (cols cg*8..cg*8+7)
        float s[8];
#pragma unroll
        for (int jj = 0; jj < 8; jj++) s[jj] = 0.f;
#pragma unroll
        for (int d4 = 0; d4 < 64; d4 += 4) {
            float4 a4 = *(float4*)&As[r][d4];
#pragma unroll
            for (int jj = 0; jj < 8; jj++) {
                float4 k4 = *(float4*)&Kc[cg * 8 + jj][d4];
                s[jj] += a4.x * k4.x + a4.y * k4.y + a4.z * k4.z + a4.w * k4.w;
            }
        }

        // online softmax over the chunk
        float mloc = s[0];
#pragma unroll
        for (int jj = 1; jj < 8; jj++) mloc = fmaxf(mloc, s[jj]);
        mloc = fmaxf(mloc, __shfl_xor_sync(0xffffffffu, mloc, 1));
        mloc = fmaxf(mloc, __shfl_xor_sync(0xffffffffu, mloc, 2));
        float mnew = fmaxf(mrun, mloc);
        float corr = __expf(mrun - mnew);
        float sl = 0.f;
#pragma unroll
        for (int jj = 0; jj < 8; jj++) {
            float p = __expf(s[jj] - mnew);
            P[r][cg * 8 + jj] = p;
            sl += p;
        }
        sl += __shfl_xor_sync(0xffffffffu, sl, 1);
        sl += __shfl_xor_sync(0xffffffffu, sl, 2);
        srun = srun * corr + sl;
#pragma unroll
        for (int i = 0; i < 16; i++) acc[i] *= corr;
        mrun = mnew;
        __syncwarp();

        // accumulate: this thread owns dims d = cg*16 .. cg*16+15
#pragma unroll 4
        for (int j = 0; j < 32; j++) {
            float p = P[r][j];
            float4 v0 = *(float4*)&Vc[j][cg * 16];
            float4 v1 = *(float4*)&Vc[j][cg * 16 + 4];
            float4 v2 = *(float4*)&Vc[j][cg * 16 + 8];
            float4 v3 = *(float4*)&Vc[j][cg * 16 + 12];
            acc[0]  = fmaf(p, v0.x, acc[0]);  acc[1]  = fmaf(p, v0.y, acc[1]);
            acc[2]  = fmaf(p, v0.z, acc[2]);  acc[3]  = fmaf(p, v0.w, acc[3]);
            acc[4]  = fmaf(p, v1.x, acc[4]);  acc[5]  = fmaf(p, v1.y, acc[5]);
            acc[6]  = fmaf(p, v1.z, acc[6]);  acc[7]  = fmaf(p, v1.w, acc[7]);
            acc[8]  = fmaf(p, v2.x, acc[8]);  acc[9]  = fmaf(p, v2.y, acc[9]);
            acc[10] = fmaf(p, v2.z, acc[10]); acc[11] = fmaf(p, v2.w, acc[11]);
            acc[12] = fmaf(p, v3.x, acc[12]); acc[13] = fmaf(p, v3.y, acc[13]);
            acc[14] = fmaf(p, v3.z, acc[14]); acc[15] = fmaf(p, v3.w, acc[15]);
        }
        __syncthreads();
    }

    float inv = 1.f / srun;
    float* po = Ob + (long long)r * 64 + cg * 16;
#pragma unroll
    for (int g = 0; g < 4; g++) {
        float4 o = make_float4(acc[g * 4] * inv, acc[g * 4 + 1] * inv,
                               acc[g * 4 + 2] * inv, acc[g * 4 + 3] * inv);
        *(float4*)(po + g * 4) = o;
    }
}

// ---------------- landmark means ----------------
__global__ void landmark_kernel(const float* __restrict__ src, float* __restrict__ dst)
{
    int m = blockIdx.x, bh = blockIdx.y, d = threadIdx.x;
    const float* p = src + ((long long)bh * N_ + (long long)m * L_) * DH_ + d;
    float s = 0.f;
#pragma unroll
    for (int i = 0; i < L_; i++) s += p[i * DH_];
    dst[((long long)bh * M_ + m) * DH_ + d] = s * (1.f / (float)L_);
}

// ---------------- softmax helpers ----------------
__device__ __forceinline__ float warpMaxRed(float v) {
#pragma unroll
    for (int o = 16; o; o >>= 1) v = fmaxf(v, __shfl_xor_sync(0xffffffffu, v, o));
    return v;
}
__device__ __forceinline__ float warpSumRed(float v) {
#pragma unroll
    for (int o = 16; o; o >>= 1) v += __shfl_xor_sync(0xffffffffu, v, o);
    return v;
}

// rows of length 256, warp per row, 8 rows per block
__global__ __launch_bounds__(256) void softmax_rows256(float* __restrict__ A)
{
    int warp = threadIdx.x >> 5, lane = threadIdx.x & 31;
    long long row = (long long)blockIdx.x * 8 + warp;
    float* p = A + row * 256;
    float4 v0 = *(float4*)(p + lane * 8);
    float4 v1 = *(float4*)(p + lane * 8 + 4);
    float mx = fmaxf(fmaxf(fmaxf(v0.x, v0.y), fmaxf(v0.z, v0.w)),
                     fmaxf(fmaxf(v1.x, v1.y), fmaxf(v1.z, v1.w)));
    mx = warpMaxRed(mx);
    v0.x = __expf(v0.x - mx); v0.y = __expf(v0.y - mx);
    v0.z = __expf(v0.z - mx); v0.w = __expf(v0.w - mx);
    v1.x = __expf(v1.x - mx); v1.y = __expf(v1.y - mx);
    v1.z = __expf(v1.z - mx); v1.w = __expf(v1.w - mx);
    float sm = v0.x + v0.y + v0.z + v0.w + v1.x + v1.y + v1.z + v1.w;
    sm = warpSumRed(sm);
    float inv = 1.f / sm;
    v0.x *= inv; v0.y *= inv; v0.z *= inv; v0.w *= inv;
    v1.x *= inv; v1.y *= inv; v1.z *= inv; v1.w *= inv;
    *(float4*)(p + lane * 8) = v0;
    *(float4*)(p + lane * 8 + 4) = v1;
}

// ---------------- pinv support ----------------
__global__ void init_max_kernel() { gMaxBits = 0; }

__global__ __launch_bounds__(256) void colmax_kernel(const float* __restrict__ A2)
{
    int bh = blockIdx.x, j = threadIdx.x;
    const float* p = A2 + ((long long)bh << 16) + j;
    float s = 0.f;
#pragma unroll 8
    for (int i = 0; i < 256; i++) s += p[i << 8];
    atomicMax(&gMaxBits, __float_as_int(s));  // sums positive -> int order == float order
}

__global__ __launch_bounds__(256) void zinit_kernel(const float* __restrict__ A2,
                                                    float* __restrict__ Z)
{
    int idx = blockIdx.x * 256 + threadIdx.x;
    float inv = 1.f / __int_as_float(gMaxBits);
    int bh = idx >> 16, r = idx & 65535, i = r >> 8, j = r & 255;
    Z[idx] = A2[(bh << 16) + (j << 8) + i] * inv;
}

__global__ __launch_bounds__(256) void ew7_kernel(const float* __restrict__ X,
                                                  float* __restrict__ U)
{
    int idx = blockIdx.x * 256 + threadIdx.x;
    int r = idx & 65535;
    float v = -X[idx];
    if ((r >> 8) == (r & 255)) v += 7.f;
    U[idx] = v;
}

// ---------------- depthwise conv(k=33) + add + concat heads ----------------
__global__ __launch_bounds__(256) void convcat_kernel(
    const float* __restrict__ V, const float* __restrict__ OH,
    const float* __restrict__ ker, float* __restrict__ CAT)
{
    int b = blockIdx.z, h = blockIdx.y, n0 = blockIdx.x * 64;
    int bh = b * H_ + h;
    __shared__ float sV[96][64];
    __shared__ float kw[33];
    int t = threadIdx.x;
    if (t < 33) kw[t] = ker[h * 33 + t];
    const float* Vb = V + (long long)bh * N_ * DH_;
    for (int idx = t; idx < 96 * 16; idx += 256) {
        int r = idx >> 4;
        int c4 = (idx & 15) * 4;
        int n = n0 - 16 + r;
        float4 val = make_float4(0.f, 0.f, 0.f, 0.f);
        if (n >= 0 && n < N_) val = *(const float4*)(Vb + (long long)n * DH_ + c4);
        *(float4*)&sV[r][c4] = val;
    }
    __syncthreads();
    int d = t & 63, nl0 = t >> 6;
#pragma unroll
    for (int ii = 0; ii < 16; ii++) {
        int nl = nl0 + ii * 4;
        float acc = 0.f;
#pragma unroll
        for (int tt = 0; tt < 33; tt++) acc = fmaf(sV[nl + tt][d], kw[tt], acc);
        int n = n0 + nl;
        float o = OH[((long long)bh * N_ + n) * DH_ + d] + acc;
        CAT[((long long)(b * N_ + n)) * 512 + h * 64 + d] = o;
    }
}

// ---------------- host ----------------
extern "C" void kernel_launch(void* const* d_in, const int* in_sizes, int n_in,
                              void* d_out, int out_size)
{
    const float* x     = (const float*)d_in[0];   // [4,8192,512]
    const float* wqkv  = (const float*)d_in[1];   // [512,1536]
    const float* wout  = (const float*)d_in[2];   // [512,512]
    const float* bout  = (const float*)d_in[3];   // [512]
    const float* rker  = (const float*)d_in[4];   // [8,1,33,1]
    float* out = (float*)d_out;                   // [4,8192,512]

    float *pQ, *pK, *pV, *pQL, *pKL, *pA2, *pZ, *pZ2, *pX, *pU1, *pU2;
    float *pA3V, *pW, *pOH, *pCAT;
    cudaGetSymbolAddress((void**)&pQ,  gQ);
    cudaGetSymbolAddress((void**)&pK,  gK);
    cudaGetSymbolAddress((void**)&pV,  gV);
    cudaGetSymbolAddress((void**)&pQL, gQL);
    cudaGetSymbolAddress((void**)&pKL, gKL);
    cudaGetSymbolAddress((void**)&pA2, gA2);
    cudaGetSymbolAddress((void**)&pZ,  gZ);
    cudaGetSymbolAddress((void**)&pZ2, gZ2);
    cudaGetSymbolAddress((void**)&pX,  gX);
    cudaGetSymbolAddress((void**)&pU1, gU1);
    cudaGetSymbolAddress((void**)&pU2, gU2);
    cudaGetSymbolAddress((void**)&pA3V, gA3V);
    cudaGetSymbolAddress((void**)&pW,  gW);
    cudaGetSymbolAddress((void**)&pOH, gOH);
    cudaGetSymbolAddress((void**)&pCAT, gCAT);

    // 1) qkv = x @ w_qkv, epilogue scatters to Q(scaled)/K/V [BH,N,64]
    gemm_qkv<<<dim3(256, 12, 1), 256>>>(x, wqkv, pQ, pK, pV);
    // 2) landmarks
    landmark_kernel<<<dim3(M_, BH_, 1), DH_>>>(pQ, pQL);
    landmark_kernel<<<dim3(M_, BH_, 1), DH_>>>(pK, pKL);
    // 3) attn2 = softmax(QL @ KL^T)
    gemm_nt64<<<dim3(2, 2, BH_), 256>>>(pQL, pKL, pA2, 256,
                                        (long long)M_ * DH_, (long long)M_ * DH_,
                                        (long long)M_ * M_);
    softmax_rows256<<<1024, 256>>>(pA2);
    // 4) pinv init: z = attn2^T / max_col_sum (row sums == 1)
    init_max_kernel<<<1, 1>>>();
    colmax_kernel<<<BH_, 256>>>(pA2);
    zinit_kernel<<<8192, 256>>>(pA2, pZ);
    // 5) 6 Newton-Schulz iterations
    float* zin = pZ;
    float* zout = pZ2;
    for (int it = 0; it < 6; it++) {
        gemm_nn<<<dim3(2, 2, BH_), 256>>>(pA2, zin, pX, nullptr,
                                          256, 256, 256, 65536, 65536, 65536, 1.f, 0.f);
        ew7_kernel<<<8192, 256>>>(pX, pU1);                                   // U1 = 7I - X
        gemm_nn<<<dim3(2, 2, BH_), 256>>>(pX, pU1, pU2, nullptr,
                                          256, 256, 256, 65536, 65536, 65536, -1.f, 15.f);
        gemm_nn<<<dim3(2, 2, BH_), 256>>>(pX, pU2, pU1, nullptr,
                                          256, 256, 256, 65536, 65536, 65536, -1.f, 13.f);
        gemm_nn<<<dim3(2, 2, BH_), 256>>>(zin, pU1, zout, nullptr,
                                          256, 256, 256, 65536, 65536, 65536, 0.25f, 0.f);
        float* tmp = zin; zin = zout; zout = tmp;
    }
    // 6) A3V = softmax(QL @ K^T) @ V, fused flash-style (no attn3 materialization)
    fused_attn<<<dim3(4, BH_), 256>>>(pQL, pK, pV, pA3V,
                                      N_ / 32, (long long)M_ * DH_,
                                      (long long)N_ * DH_, (long long)M_ * DH_);
    // 7) W = attn2_inv @ A3V
    gemm_nn<<<dim3(2, 1, BH_), 256>>>(zin, pA3V, pW, nullptr,
                                      256, 64, 256,
                                      65536, (long long)M_ * DH_,
                                      (long long)M_ * DH_, 1.f, 0.f);
    // 8) OH = softmax(Q @ KL^T) @ W, fused flash-style (no attn1 materialization)
    fused_attn<<<dim3(128, BH_), 256>>>(pQ, pKL, pW, pOH,
                                        M_ / 32, (long long)N_ * DH_,
                                        (long long)M_ * DH_, (long long)N_ * DH_);
    // 9) residual depthwise conv + concat heads
    convcat_kernel<<<dim3(128, H_, B_), 256>>>(pV, pOH, rker, pCAT);
    // 10) out = CAT @ w_out + b_out
    gemm_nn<<<dim3(256, 4, 1), 256>>>(pCAT, wout, out, bout,
                                      32768, 512, 512, 0, 0, 0, 1.f, 0.f);
}

// round 5
// speedup vs baseline: 1.1781x; 1.1781x over previous
#include <cuda_runtime.h>
#include <cstdint>
#include <math.h>

// Problem constants
#define B_   4
#define H_   8
#define N_   8192
#define DH_  64
#define M_   256
#define L_   32
#define BH_  32

// ---------------- scratch (device globals; no allocation anywhere) ----------------
__device__ float gQ[16777216];     // [BH,N,DH] (pre-scaled by dh^-0.5)
__device__ float gK[16777216];
__device__ float gV[16777216];
__device__ float gQL[524288];      // [BH,M,DH]
__device__ float gKL[524288];
__device__ float gA2[2097152];     // [BH,M,M] softmaxed
__device__ float gZ [2097152];
__device__ float gZT[2097152];
__device__ float gZ2[2097152];
__device__ float gZ2T[2097152];
__device__ float gX [2097152];
__device__ float gT1[2097152];     // U1T / U3T
__device__ float gT2[2097152];     // U2T
__device__ float gA3V[524288];
__device__ float gW [524288];
__device__ float gOH[16777216];
__device__ float gCAT[16777216];
__device__ float gWqkvT[786432];   // [1536,512]
__device__ float gWoutT[262144];   // [512,512]
__device__ int   gMaxBits;

// ================= mma.sync tf32 helpers =================
__device__ __forceinline__ uint32_t f2tf32(float v) {
    uint32_t u;
    asm("cvt.rna.tf32.f32 %0, %1;" : "=r"(u) : "f"(v));
    return u;
}
__device__ __forceinline__ void mma_16x8x8(float* c, const uint32_t* a, const uint32_t* b) {
    asm volatile("mma.sync.aligned.m16n8k8.row.col.f32.tf32.tf32.f32 "
                 "{%0,%1,%2,%3}, {%4,%5,%6,%7}, {%8,%9}, {%0,%1,%2,%3};"
                 : "+f"(c[0]), "+f"(c[1]), "+f"(c[2]), "+f"(c[3])
                 : "r"(a[0]), "r"(a[1]), "r"(a[2]), "r"(a[3]), "r"(b[0]), "r"(b[1]));
}

// Stage A chunk: 128 rows x 32 k from g (row-major, ld=ldg) into fragment-permuted tf32.
// Layout: [(warp_m*4+mi)*4+kf][lane][reg]  (reg fastest, 4 per lane)
__device__ __forceinline__ void stage_A(const float* __restrict__ g, int ldg,
                                        uint32_t* __restrict__ sm, int tid) {
#pragma unroll
    for (int i = 0; i < 4; i++) {
        int f = tid + i * 256;
        int r = f >> 3;
        int k = (f & 7) * 4;
        float4 v = *(const float4*)(g + (long long)r * ldg + k);
        int wm = r >> 6, rl6 = r & 63;
        int mi = rl6 >> 4, rl = rl6 & 15;
        int rowsel = rl >> 3;                       // contributes +1 to reg
        int base_unit = (wm * 16 + mi * 4 + (k >> 3)) * 128 + (rl & 7) * 16 + rowsel;
        int khalf = 2 * ((k >> 2) & 1);             // contributes +2 to reg
        float vv[4] = {v.x, v.y, v.z, v.w};
#pragma unroll
        for (int j = 0; j < 4; j++)
            sm[base_unit + j * 4 + khalf] = f2tf32(vv[j]);
    }
}

// Stage B chunk: 128 n-rows x 32 k from g (row-major NT) into fragment-permuted tf32.
// Layout: [(warp_n*4+nf)*4+kf][lane][reg]  (2 regs per lane)
__device__ __forceinline__ void stage_B(const float* __restrict__ g, int ldg,
                                        uint32_t* __restrict__ sm, int tid) {
#pragma unroll
    for (int i = 0; i < 4; i++) {
        int f = tid + i * 256;
        int c = f >> 3;
        int k = (f & 7) * 4;
        float4 v = *(const float4*)(g + (long long)c * ldg + k);
        int wn = c >> 5, cl = c & 31;
        int nf = cl >> 3, gg = cl & 7;
        int base_unit = (wn * 16 + nf * 4 + (k >> 3)) * 64 + gg * 8;
        int reg = (k >> 2) & 1;
        float vv[4] = {v.x, v.y, v.z, v.w};
#pragma unroll
        for (int j = 0; j < 4; j++)
            sm[base_unit + j * 2 + reg] = f2tf32(vv[j]);
    }
}

#define PS 132  // pad stride (floats)

// ======== generic tf32 mma NT GEMM ========
// C  = s *(A @ Bop^T) + dI*I (+bias)   row-major [Md,Nd]
// CT = sT*(A @ Bop^T)^T + dT*I         row-major [Nd,Md]
// A: [Md,Kd] rm; Bop: [Nd,Kd] rm. 128x128 tiles, K chunks of 32. Dims multiples of 128.
__global__ __launch_bounds__(256) void gemm_mma(
    const float* __restrict__ A, const float* __restrict__ Bop,
    float* C, float* CT, const float* __restrict__ bias,
    int Kd, int ldc, int ldct,
    long long sA, long long sB, long long sC, long long sCT,
    float s, float dI, float sT, float dT)
{
    extern __shared__ uint32_t dynu[];
    const int tid = threadIdx.x;
    const int wid = tid >> 5, lane = tid & 31;
    const int warp_m = wid >> 2, warp_n = wid & 3;
    const int g = lane >> 2, t = lane & 3;
    const int m0 = blockIdx.x * 128, n0 = blockIdx.y * 128;
    const float* Ab = A + blockIdx.z * sA + (long long)m0 * Kd;
    const float* Bb = Bop + blockIdx.z * sB + (long long)n0 * Kd;

    uint32_t* smA[2] = {dynu, dynu + 4096};
    uint32_t* smB[2] = {dynu + 8192, dynu + 12288};

    float acc[4][4][4];
#pragma unroll
    for (int mi = 0; mi < 4; mi++)
#pragma unroll
        for (int nf = 0; nf < 4; nf++)
#pragma unroll
            for (int rr = 0; rr < 4; rr++) acc[mi][nf][rr] = 0.f;

    const int nCh = Kd >> 5;
    stage_A(Ab, Kd, smA[0], tid);
    stage_B(Bb, Kd, smB[0], tid);
    __syncthreads();

    for (int c = 0; c < nCh; c++) {
        if (c + 1 < nCh) {
            stage_A(Ab + (c + 1) * 32, Kd, smA[(c + 1) & 1], tid);
            stage_B(Bb + (c + 1) * 32, Kd, smB[(c + 1) & 1], tid);
        }
        const uint32_t* cA = smA[c & 1];
        const uint32_t* cB = smB[c & 1];
#pragma unroll
        for (int kf = 0; kf < 4; kf++) {
            uint32_t a[4][4], b[4][2];
#pragma unroll
            for (int mi = 0; mi < 4; mi++) {
                uint4 av = *(const uint4*)(cA + (warp_m * 16 + mi * 4 + kf) * 128 + lane * 4);
                a[mi][0] = av.x; a[mi][1] = av.y; a[mi][2] = av.z; a[mi][3] = av.w;
            }
#pragma unroll
            for (int nf = 0; nf < 4; nf++) {
                uint2 bv = *(const uint2*)(cB + (warp_n * 16 + nf * 4 + kf) * 64 + lane * 2);
                b[nf][0] = bv.x; b[nf][1] = bv.y;
            }
#pragma unroll
            for (int mi = 0; mi < 4; mi++)
#pragma unroll
                for (int nf = 0; nf < 4; nf++)
                    mma_16x8x8(acc[mi][nf], a[mi], b[nf]);
        }
        __syncthreads();
    }

    // epilogue via smem pad
    float* pad = (float*)dynu;
#pragma unroll
    for (int mi = 0; mi < 4; mi++) {
        int r0 = warp_m * 64 + mi * 16 + g;
#pragma unroll
        for (int nf = 0; nf < 4; nf++) {
            int c0 = warp_n * 32 + nf * 8 + 2 * t;
            pad[r0 * PS + c0]           = acc[mi][nf][0];
            pad[r0 * PS + c0 + 1]       = acc[mi][nf][1];
            pad[(r0 + 8) * PS + c0]     = acc[mi][nf][2];
            pad[(r0 + 8) * PS + c0 + 1] = acc[mi][nf][3];
        }
    }
    __syncthreads();

    if (C) {
        float* Cb = C + blockIdx.z * sC;
#pragma unroll
        for (int rr = 0; rr < 16; rr++) {
            int rl = rr * 8 + wid;
            int grow = m0 + rl;
            float4 v = *(float4*)(pad + rl * PS + lane * 4);
            int gc = n0 + lane * 4;
            float o[4] = {v.x, v.y, v.z, v.w};
#pragma unroll
            for (int u = 0; u < 4; u++) {
                o[u] *= s;
                if (dI != 0.f && grow == gc + u) o[u] += dI;
                if (bias) o[u] += __ldg(bias + gc + u);
            }
            *(float4*)(Cb + (long long)grow * ldc + gc) = make_float4(o[0], o[1], o[2], o[3]);
        }
    }
    if (CT) {
        float* CTb = CT + blockIdx.z * sCT;
#pragma unroll
        for (int rr = 0; rr < 16; rr++) {
            int cl = rr * 8 + wid;          // output row = original col
            int gcol = n0 + cl;
            int rbase = lane * 4;
            float o[4];
#pragma unroll
            for (int u = 0; u < 4; u++) {
                float v = sT * pad[(rbase + u) * PS + cl];
                if (dT != 0.f && gcol == m0 + rbase + u) v += dT;
                o[u] = v;
            }
            *(float4*)(CTb + (long long)gcol * ldct + m0 + rbase) =
                make_float4(o[0], o[1], o[2], o[3]);
        }
    }
}

// ======== tf32 mma qkv GEMM: x[32768,512] @ wqkvT[1536,512]^T, scatter epilogue ========
__global__ __launch_bounds__(256) void gemm_mma_qkv(
    const float* __restrict__ A, const float* __restrict__ Bop,
    float* __restrict__ Q, float* __restrict__ Kp, float* __restrict__ V)
{
    extern __shared__ uint32_t dynu[];
    const int tid = threadIdx.x;
    const int wid = tid >> 5, lane = tid & 31;
    const int warp_m = wid >> 2, warp_n = wid & 3;
    const int g = lane >> 2, t = lane & 3;
    const int m0 = blockIdx.x * 128, n0 = blockIdx.y * 128;
    const float* Ab = A + (long long)m0 * 512;
    const float* Bb = Bop + (long long)n0 * 512;

    uint32_t* smA[2] = {dynu, dynu + 4096};
    uint32_t* smB[2] = {dynu + 8192, dynu + 12288};

    float acc[4][4][4];
#pragma unroll
    for (int mi = 0; mi < 4; mi++)
#pragma unroll
        for (int nf = 0; nf < 4; nf++)
#pragma unroll
            for (int rr = 0; rr < 4; rr++) acc[mi][nf][rr] = 0.f;

    stage_A(Ab, 512, smA[0], tid);
    stage_B(Bb, 512, smB[0], tid);
    __syncthreads();

    for (int c = 0; c < 16; c++) {
        if (c + 1 < 16) {
            stage_A(Ab + (c + 1) * 32, 512, smA[(c + 1) & 1], tid);
            stage_B(Bb + (c + 1) * 32, 512, smB[(c + 1) & 1], tid);
        }
        const uint32_t* cA = smA[c & 1];
        const uint32_t* cB = smB[c & 1];
#pragma unroll
        for (int kf = 0; kf < 4; kf++) {
            uint32_t a[4][4], b[4][2];
#pragma unroll
            for (int mi = 0; mi < 4; mi++) {
                uint4 av = *(const uint4*)(cA + (warp_m * 16 + mi * 4 + kf) * 128 + lane * 4);
                a[mi][0] = av.x; a[mi][1] = av.y; a[mi][2] = av.z; a[mi][3] = av.w;
            }
#pragma unroll
            for (int nf = 0; nf < 4; nf++) {
                uint2 bv = *(const uint2*)(cB + (warp_n * 16 + nf * 4 + kf) * 64 + lane * 2);
                b[nf][0] = bv.x; b[nf][1] = bv.y;
            }
#pragma unroll
            for (int mi = 0; mi < 4; mi++)
#pragma unroll
                for (int nf = 0; nf < 4; nf++)
                    mma_16x8x8(acc[mi][nf], a[mi], b[nf]);
        }
        __syncthreads();
    }

    float* pad = (float*)dynu;
#pragma unroll
    for (int mi = 0; mi < 4; mi++) {
        int r0 = warp_m * 64 + mi * 16 + g;
#pragma unroll
        for (int nf = 0; nf < 4; nf++) {
            int c0 = warp_n * 32 + nf * 8 + 2 * t;
            pad[r0 * PS + c0]           = acc[mi][nf][0];
            pad[r0 * PS + c0 + 1]       = acc[mi][nf][1];
            pad[(r0 + 8) * PS + c0]     = acc[mi][nf][2];
            pad[(r0 + 8) * PS + c0 + 1] = acc[mi][nf][3];
        }
    }
    __syncthreads();

    const int which = n0 >> 9;                 // whole tile within one of q/k/v
    float* dst = (which == 0) ? Q : ((which == 1) ? Kp : V);
    const float sc = (which == 0) ? 0.125f : 1.f;
#pragma unroll
    for (int rr = 0; rr < 16; rr++) {
        int rl = rr * 8 + wid;
        int grow = m0 + rl;
        int bidx = grow >> 13, n = grow & (N_ - 1);
        int gc = n0 + lane * 4;
        int h = (gc >> 6) & 7, d = gc & 63;
        float4 v = *(float4*)(pad + rl * PS + lane * 4);
        v.x *= sc; v.y *= sc; v.z *= sc; v.w *= sc;
        long long addr = ((long long)(bidx * 8 + h) * N_ + n) * 64 + d;
        *(float4*)(dst + addr) = v;
    }
}

// ---------------- weight transpose: dst[C,R] = src[R,C]^T ----------------
__global__ void transpose_kernel(const float* __restrict__ src, float* __restrict__ dst,
                                 int R, int C)
{
    __shared__ float tbuf[32][33];
    int c0 = blockIdx.x * 32, r0 = blockIdx.y * 32;
    int x = threadIdx.x, y = threadIdx.y;
#pragma unroll
    for (int i = 0; i < 32; i += 8) tbuf[y + i][x] = src[(long long)(r0 + y + i) * C + c0 + x];
    __syncthreads();
#pragma unroll
    for (int i = 0; i < 32; i += 8) dst[(long long)(c0 + y + i) * R + r0 + x] = tbuf[x][y + i];
}

// ---------------- FFMA NN GEMM (small W = Z @ A3V only) ----------------
__global__ __launch_bounds__(256) void gemm_nn(
    const float* __restrict__ A, const float* __restrict__ B,
    float* __restrict__ C, int Md, int Nd, int Kd,
    long long sA, long long sB, long long sC)
{
    A += (long long)blockIdx.z * sA;
    B += (long long)blockIdx.z * sB;
    C += (long long)blockIdx.z * sC;
    const int m0 = blockIdx.x * 128;
    const int n0 = blockIdx.y * 128;
    const int tid = threadIdx.x;
    const int tx = tid & 15, ty = tid >> 4;
    __shared__ float As[8][132];
    __shared__ float Bs[8][128];
    float acc[8][8];
#pragma unroll
    for (int i = 0; i < 8; i++)
#pragma unroll
        for (int j = 0; j < 8; j++) acc[i][j] = 0.f;
    const int ar = tid >> 1, ac = (tid & 1) * 4;
    const int bk = tid >> 5, bn = (tid & 31) * 4;
    const bool bok = (n0 + bn < Nd);
    for (int kk = 0; kk < Kd; kk += 8) {
        float4 av = *(const float4*)(A + (long long)(m0 + ar) * Kd + kk + ac);
        float4 bv = make_float4(0.f, 0.f, 0.f, 0.f);
        if (bok) bv = *(const float4*)(B + (long long)(kk + bk) * Nd + n0 + bn);
        As[ac + 0][ar] = av.x; As[ac + 1][ar] = av.y;
        As[ac + 2][ar] = av.z; As[ac + 3][ar] = av.w;
        *(float4*)&Bs[bk][bn] = bv;
        __syncthreads();
#pragma unroll
        for (int k = 0; k < 8; k++) {
            float a[8], b[8];
            *(float4*)&a[0] = *(const float4*)&As[k][ty * 8];
            *(float4*)&a[4] = *(const float4*)&As[k][ty * 8 + 4];
            *(float4*)&b[0] = *(const float4*)&Bs[k][tx * 8];
            *(float4*)&b[4] = *(const float4*)&Bs[k][tx * 8 + 4];
#pragma unroll
            for (int i = 0; i < 8; i++)
#pragma unroll
                for (int j = 0; j < 8; j++)
                    acc[i][j] = fmaf(a[i], b[j], acc[i][j]);
        }
        __syncthreads();
    }
#pragma unroll
    for (int i = 0; i < 8; i++) {
        int row = m0 + ty * 8 + i;
        if (row >= Md) continue;
#pragma unroll
        for (int jg = 0; jg < 8; jg += 4) {
            int col = n0 + tx * 8 + jg;
            if (col >= Nd) continue;
            float4 o = make_float4(acc[i][jg], acc[i][jg + 1], acc[i][jg + 2], acc[i][jg + 3]);
            *(float4*)(C + (long long)row * Nd + col) = o;
        }
    }
}

// ---------------- fused online-softmax attention: Out = softmax(A @ B^T) @ V ----------
__global__ __launch_bounds__(256) void fused_attn(
    const float* __restrict__ Arows, const float* __restrict__ Bmat,
    const float* __restrict__ Vmat, float* __restrict__ Out,
    int nChunks, long long sA, long long sB, long long sO)
{
    const int bh = blockIdx.y;
    const int row0 = blockIdx.x * 64;
    const float* Ab = Arows + (long long)bh * sA + (long long)row0 * 64;
    const float* Bb = Bmat + (long long)bh * sB;
    const float* Vb = Vmat + (long long)bh * sB;
    float* Ob = Out + (long long)bh * sO + (long long)row0 * 64;

    __shared__ float As[64][68];
    __shared__ float Kc[32][68];
    __shared__ float Vc[32][68];
    __shared__ float P[64][36];

    const int tid = threadIdx.x;
    const int r = tid >> 2;
    const int cg = tid & 3;
#pragma unroll
    for (int k = 0; k < 4; k++) {
        int f = tid + k * 256;
        int rr = f >> 4, c4 = (f & 15) * 4;
        *(float4*)&As[rr][c4] = *(const float4*)(Ab + (long long)rr * 64 + c4);
    }
    float acc[16];
#pragma unroll
    for (int i = 0; i < 16; i++) acc[i] = 0.f;
    float mrun = -3.0e38f, srun = 0.f;

    for (int ch = 0; ch < nChunks; ch++) {
        const float* Kg = Bb + (long long)ch * 32 * 64;
        const float* Vg = Vb + (long long)ch * 32 * 64;
#pragma unroll
        for (int k = 0; k < 2; k++) {
            int f = tid + k * 256;
            int jj = f >> 4, c4 = (f & 15) * 4;
            *(float4*)&Kc[jj][c4] = *(const float4*)(Kg + jj * 64 + c4);
            *(float4*)&Vc[jj][c4] = *(const float4*)(Vg + jj * 64 + c4);
        }
        __syncthreads();
        float s[8];
#pragma unroll
        for (int jj = 0; jj < 8; jj++) s[jj] = 0.f;
#pragma unroll
        for (int d4 = 0; d4 < 64; d4 += 4) {
            float4 a4 = *(float4*)&As[r][d4];
#pragma unroll
            for (int jj = 0; jj < 8; jj++) {
                float4 k4 = *(float4*)&Kc[cg * 8 + jj][d4];
                s[jj] += a4.x * k4.x + a4.y * k4.y + a4.z * k4.z + a4.w * k4.w;
            }
        }
        float mloc = s[0];
#pragma unroll
        for (int jj = 1; jj < 8; jj++) mloc = fmaxf(mloc, s[jj]);
        mloc = fmaxf(mloc, __shfl_xor_sync(0xffffffffu, mloc, 1));
        mloc = fmaxf(mloc, __shfl_xor_sync(0xffffffffu, mloc, 2));
        float mnew = fmaxf(mrun, mloc);
        float corr = __expf(mrun - mnew);
        float sl = 0.f;
#pragma unroll
        for (int jj = 0; jj < 8; jj++) {
            float p = __expf(s[jj] - mnew);
            P[r][cg * 8 + jj] = p;
            sl += p;
        }
        sl += __shfl_xor_sync(0xffffffffu, sl, 1);
        sl += __shfl_xor_sync(0xffffffffu, sl, 2);
        srun = srun * corr + sl;
#pragma unroll
        for (int i = 0; i < 16; i++) acc[i] *= corr;
        mrun = mnew;
        __syncwarp();
#pragma unroll 4
        for (int j = 0; j < 32; j++) {
            float p = P[r][j];
            float4 v0 = *(float4*)&Vc[j][cg * 16];
            float4 v1 = *(float4*)&Vc[j][cg * 16 + 4];
            float4 v2 = *(float4*)&Vc[j][cg * 16 + 8];
            float4 v3 = *(float4*)&Vc[j][cg * 16 + 12];
            acc[0]  = fmaf(p, v0.x, acc[0]);  acc[1]  = fmaf(p, v0.y, acc[1]);
            acc[2]  = fmaf(p, v0.z, acc[2]);  acc[3]  = fmaf(p, v0.w, acc[3]);
            acc[4]  = fmaf(p, v1.x, acc[4]);  acc[5]  = fmaf(p, v1.y, acc[5]);
            acc[6]  = fmaf(p, v1.z, acc[6]);  acc[7]  = fmaf(p, v1.w, acc[7]);
            acc[8]  = fmaf(p, v2.x, acc[8]);  acc[9]  = fmaf(p, v2.y, acc[9]);
            acc[10] = fmaf(p, v2.z, acc[10]); acc[11] = fmaf(p, v2.w, acc[11]);
            acc[12] = fmaf(p, v3.x, acc[12]); acc[13] = fmaf(p, v3.y, acc[13]);
            acc[14] = fmaf(p, v3.z, acc[14]); acc[15] = fmaf(p, v3.w, acc[15]);
        }
        __syncthreads();
    }
    float inv = 1.f / srun;
    float* po = Ob + (long long)r * 64 + cg * 16;
#pragma unroll
    for (int gg = 0; gg < 4; gg++) {
        float4 o = make_float4(acc[gg * 4] * inv, acc[gg * 4 + 1] * inv,
                               acc[gg * 4 + 2] * inv, acc[gg * 4 + 3] * inv);
        *(float4*)(po + gg * 4) = o;
    }
}

// ---------------- landmark means ----------------
__global__ void landmark_kernel(const float* __restrict__ src, float* __restrict__ dst)
{
    int m = blockIdx.x, bh = blockIdx.y, d = threadIdx.x;
    const float* p = src + ((long long)bh * N_ + (long long)m * L_) * DH_ + d;
    float s = 0.f;
#pragma unroll
    for (int i = 0; i < L_; i++) s += p[i * DH_];
    dst[((long long)bh * M_ + m) * DH_ + d] = s * (1.f / (float)L_);
}

__device__ __forceinline__ float warpMaxRed(float v) {
#pragma unroll
    for (int o = 16; o; o >>= 1) v = fmaxf(v, __shfl_xor_sync(0xffffffffu, v, o));
    return v;
}
__device__ __forceinline__ float warpSumRed(float v) {
#pragma unroll
    for (int o = 16; o; o >>= 1) v += __shfl_xor_sync(0xffffffffu, v, o);
    return v;
}

__global__ __launch_bounds__(256) void softmax_rows256(float* __restrict__ A)
{
    int warp = threadIdx.x >> 5, lane = threadIdx.x & 31;
    long long row = (long long)blockIdx.x * 8 + warp;
    float* p = A + row * 256;
    float4 v0 = *(float4*)(p + lane * 8);
    float4 v1 = *(float4*)(p + lane * 8 + 4);
    float mx = fmaxf(fmaxf(fmaxf(v0.x, v0.y), fmaxf(v0.z, v0.w)),
                     fmaxf(fmaxf(v1.x, v1.y), fmaxf(v1.z, v1.w)));
    mx = warpMaxRed(mx);
    v0.x = __expf(v0.x - mx); v0.y = __expf(v0.y - mx);
    v0.z = __expf(v0.z - mx); v0.w = __expf(v0.w - mx);
    v1.x = __expf(v1.x - mx); v1.y = __expf(v1.y - mx);
    v1.z = __expf(v1.z - mx); v1.w = __expf(v1.w - mx);
    float sm = v0.x + v0.y + v0.z + v0.w + v1.x + v1.y + v1.z + v1.w;
    sm = warpSumRed(sm);
    float inv = 1.f / sm;
    v0.x *= inv; v0.y *= inv; v0.z *= inv; v0.w *= inv;
    v1.x *= inv; v1.y *= inv; v1.z *= inv; v1.w *= inv;
    *(float4*)(p + lane * 8) = v0;
    *(float4*)(p + lane * 8 + 4) = v1;
}

// ---------------- pinv support ----------------
__global__ void init_max_kernel() { gMaxBits = 0; }

__global__ __launch_bounds__(256) void colmax_kernel(const float* __restrict__ A2)
{
    int bh = blockIdx.x, j = threadIdx.x;
    const float* p = A2 + ((long long)bh << 16) + j;
    float s = 0.f;
#pragma unroll 8
    for (int i = 0; i < 256; i++) s += p[i << 8];
    atomicMax(&gMaxBits, __float_as_int(s));
}

__global__ __launch_bounds__(256) void zinit_kernel(const float* __restrict__ A2,
                                                    float* __restrict__ Z,
                                                    float* __restrict__ ZT)
{
    int idx = blockIdx.x * 256 + threadIdx.x;
    float inv = 1.f / __int_as_float(gMaxBits);
    int bh = idx >> 16, r = idx & 65535, i = r >> 8, j = r & 255;
    Z[idx]  = A2[(bh << 16) + (j << 8) + i] * inv;
    ZT[idx] = A2[idx] * inv;
}

// ---------------- depthwise conv(k=33) + add + concat heads ----------------
__global__ __launch_bounds__(256) void convcat_kernel(
    const float* __restrict__ V, const float* __restrict__ OH,
    const float* __restrict__ ker, float* __restrict__ CAT)
{
    int b = blockIdx.z, h = blockIdx.y, n0 = blockIdx.x * 64;
    int bh = b * H_ + h;
    __shared__ float sV[96][64];
    __shared__ float kw[33];
    int t = threadIdx.x;
    if (t < 33) kw[t] = ker[h * 33 + t];
    const float* Vb = V + (long long)bh * N_ * DH_;
    for (int idx = t; idx < 96 * 16; idx += 256) {
        int r = idx >> 4;
        int c4 = (idx & 15) * 4;
        int n = n0 - 16 + r;
        float4 val = make_float4(0.f, 0.f, 0.f, 0.f);
        if (n >= 0 && n < N_) val = *(const float4*)(Vb + (long long)n * DH_ + c4);
        *(float4*)&sV[r][c4] = val;
    }
    __syncthreads();
    int d = t & 63, nl0 = t >> 6;
#pragma unroll
    for (int ii = 0; ii < 16; ii++) {
        int nl = nl0 + ii * 4;
        float acc = 0.f;
#pragma unroll
        for (int tt = 0; tt < 33; tt++) acc = fmaf(sV[nl + tt][d], kw[tt], acc);
        int n = n0 + nl;
        float o = OH[((long long)bh * N_ + n) * DH_ + d] + acc;
        CAT[((long long)(b * N_ + n)) * 512 + h * 64 + d] = o;
    }
}

// ---------------- host ----------------
#define DYN_SMEM (128 * PS * 4)   // 67584 B; mainloop needs 65536 B

extern "C" void kernel_launch(void* const* d_in, const int* in_sizes, int n_in,
                              void* d_out, int out_size)
{
    const float* x     = (const float*)d_in[0];
    const float* wqkv  = (const float*)d_in[1];
    const float* wout  = (const float*)d_in[2];
    const float* bout  = (const float*)d_in[3];
    const float* rker  = (const float*)d_in[4];
    float* out = (float*)d_out;

    cudaFuncSetAttribute(gemm_mma, cudaFuncAttributeMaxDynamicSharedMemorySize, DYN_SMEM);
    cudaFuncSetAttribute(gemm_mma_qkv, cudaFuncAttributeMaxDynamicSharedMemorySize, DYN_SMEM);

    float *pQ, *pK, *pV, *pQL, *pKL, *pA2, *pZ, *pZT, *pZ2, *pZ2T, *pX;
    float *pT1, *pT2, *pA3V, *pW, *pOH, *pCAT, *pWqkvT, *pWoutT;
    cudaGetSymbolAddress((void**)&pQ,  gQ);
    cudaGetSymbolAddress((void**)&pK,  gK);
    cudaGetSymbolAddress((void**)&pV,  gV);
    cudaGetSymbolAddress((void**)&pQL, gQL);
    cudaGetSymbolAddress((void**)&pKL, gKL);
    cudaGetSymbolAddress((void**)&pA2, gA2);
    cudaGetSymbolAddress((void**)&pZ,  gZ);
    cudaGetSymbolAddress((void**)&pZT, gZT);
    cudaGetSymbolAddress((void**)&pZ2, gZ2);
    cudaGetSymbolAddress((void**)&pZ2T, gZ2T);
    cudaGetSymbolAddress((void**)&pX,  gX);
    cudaGetSymbolAddress((void**)&pT1, gT1);
    cudaGetSymbolAddress((void**)&pT2, gT2);
    cudaGetSymbolAddress((void**)&pA3V, gA3V);
    cudaGetSymbolAddress((void**)&pW,  gW);
    cudaGetSymbolAddress((void**)&pOH, gOH);
    cudaGetSymbolAddress((void**)&pCAT, gCAT);
    cudaGetSymbolAddress((void**)&pWqkvT, gWqkvT);
    cudaGetSymbolAddress((void**)&pWoutT, gWoutT);

    const long long MM = (long long)M_ * M_;
    const long long MD = (long long)M_ * DH_;
    const long long ND = (long long)N_ * DH_;

    // 0) transpose weights (NT form)
    transpose_kernel<<<dim3(48, 16), dim3(32, 8)>>>(wqkv, pWqkvT, 512, 1536);
    transpose_kernel<<<dim3(16, 16), dim3(32, 8)>>>(wout, pWoutT, 512, 512);
    // 1) qkv GEMM (mma) with scatter epilogue
    gemm_mma_qkv<<<dim3(256, 12), 256, DYN_SMEM>>>(x, pWqkvT, pQ, pK, pV);
    // 2) landmarks
    landmark_kernel<<<dim3(M_, BH_), DH_>>>(pQ, pQL);
    landmark_kernel<<<dim3(M_, BH_), DH_>>>(pK, pKL);
    // 3) attn2 = softmax(QL @ KL^T) (mma NT, K=64)
    gemm_mma<<<dim3(2, 2, BH_), 256, DYN_SMEM>>>(pQL, pKL, pA2, nullptr, nullptr,
                                                 64, 256, 0, MD, MD, MM, 0,
                                                 1.f, 0.f, 0.f, 0.f);
    softmax_rows256<<<1024, 256>>>(pA2);
    // 4) pinv init
    init_max_kernel<<<1, 1>>>();
    colmax_kernel<<<BH_, 256>>>(pA2);
    zinit_kernel<<<8192, 256>>>(pA2, pZ, pZT);
    // 5) Newton-Schulz iterations (mma; B-operands are transposed copies)
    float *zin = pZ, *zinT = pZT, *zout = pZ2, *zoutT = pZ2T;
    for (int it = 0; it < 6; it++) {
        // X = A2 @ Z (Bop = ZT); C = X, CT = 7I - X^T (fused U1T)
        gemm_mma<<<dim3(2, 2, BH_), 256, DYN_SMEM>>>(pA2, zinT, pX, pT1, nullptr,
                                                     256, 256, 256, MM, MM, MM, MM,
                                                     1.f, 0.f, -1.f, 7.f);
        // U2T = (15I - X@U1)^T (Bop = U1T)
        gemm_mma<<<dim3(2, 2, BH_), 256, DYN_SMEM>>>(pX, pT1, nullptr, pT2, nullptr,
                                                     256, 256, 256, MM, MM, MM, MM,
                                                     0.f, 0.f, -1.f, 15.f);
        // U3T = (13I - X@U2)^T (Bop = U2T), into T1
        gemm_mma<<<dim3(2, 2, BH_), 256, DYN_SMEM>>>(pX, pT2, nullptr, pT1, nullptr,
                                                     256, 256, 256, MM, MM, MM, MM,
                                                     0.f, 0.f, -1.f, 13.f);
        // Znew = 0.25 * Z @ U3 (Bop = U3T); store Znew and ZnewT
        gemm_mma<<<dim3(2, 2, BH_), 256, DYN_SMEM>>>(zin, pT1, zout, zoutT, nullptr,
                                                     256, 256, 256, MM, MM, MM, MM,
                                                     0.25f, 0.f, 0.25f, 0.f);
        float* t;
        t = zin; zin = zout; zout = t;
        t = zinT; zinT = zoutT; zoutT = t;
    }
    // 6) A3V = softmax(QL @ K^T) @ V (fused, FFMA)
    fused_attn<<<dim3(4, BH_), 256>>>(pQL, pK, pV, pA3V, N_ / 32, MD, ND, MD);
    // 7) W = Zfinal @ A3V (small FFMA NN)
    gemm_nn<<<dim3(2, 1, BH_), 256>>>(zin, pA3V, pW, 256, 64, 256, MM, MD, MD);
    // 8) OH = softmax(Q @ KL^T) @ W (fused, FFMA)
    fused_attn<<<dim3(128, BH_), 256>>>(pQ, pKL, pW, pOH, M_ / 32, ND, MD, ND);
    // 9) conv + concat
    convcat_kernel<<<dim3(128, H_, B_), 256>>>(pV, pOH, rker, pCAT);
    // 10) out = CAT @ wout + bout (mma NT)
    gemm_mma<<<dim3(256, 4), 256, DYN_SMEM>>>(pCAT, pWoutT, out, nullptr, bout,
                                              512, 512, 0, 0, 0, 0, 0,
                                              1.f, 0.f, 0.f, 0.f);
}

// round 6
// speedup vs baseline: 1.2618x; 1.0711x over previous
#include <cuda_runtime.h>
#include <cstdint>
#include <math.h>

// Problem constants
#define B_   4
#define H_   8
#define N_   8192
#define DH_  64
#define M_   256
#define L_   32
#define BH_  32

// ---------------- scratch (device globals; no allocation anywhere) ----------------
__device__ float gQ[16777216];     // [BH,N,DH] (pre-scaled by dh^-0.5)
__device__ float gK[16777216];
__device__ float gV[16777216];
__device__ float gQL[524288];      // [BH,M,DH]
__device__ float gKL[524288];
__device__ float gA2[2097152];     // [BH,M,M] softmaxed (tf32-rounded)
__device__ float gZ [2097152];
__device__ float gZT[2097152];
__device__ float gZ2[2097152];
__device__ float gZ2T[2097152];
__device__ float gX [2097152];
__device__ float gT1[2097152];     // U1T / U3T
__device__ float gT2[2097152];     // U2T
__device__ float gA3V[524288];
__device__ float gW [524288];
__device__ float gOH[16777216];
__device__ float gCAT[16777216];   // rounded-x first, then conv output
__device__ float gWqkvT[786432];   // [1536,512]
__device__ float gWoutT[262144];   // [512,512]
__device__ int   gMaxBits;

// ================= helpers =================
__device__ __forceinline__ uint32_t smem_u32(const void* p) {
    uint32_t a;
    asm("{ .reg .u64 t; cvta.to.shared.u64 t, %1; cvt.u32.u64 %0, t; }" : "=r"(a) : "l"(p));
    return a;
}
__device__ __forceinline__ float tf32r(float v) {
    uint32_t u;
    asm("cvt.rna.tf32.f32 %0, %1;" : "=r"(u) : "f"(v));
    return __uint_as_float(u);
}
__device__ __forceinline__ void mma_16x8x8(float* c, const uint32_t* a, const uint32_t* b) {
    asm volatile("mma.sync.aligned.m16n8k8.row.col.f32.tf32.tf32.f32 "
                 "{%0,%1,%2,%3}, {%4,%5,%6,%7}, {%8,%9}, {%0,%1,%2,%3};"
                 : "+f"(c[0]), "+f"(c[1]), "+f"(c[2]), "+f"(c[3])
                 : "r"(a[0]), "r"(a[1]), "r"(a[2]), "r"(a[3]), "r"(b[0]), "r"(b[1]));
}
__device__ __forceinline__ void cp16(uint32_t dst, const float* src) {
    asm volatile("cp.async.cg.shared.global [%0], [%1], 16;" :: "r"(dst), "l"(src) : "memory");
}
#define CP_COMMIT() asm volatile("cp.async.commit_group;" ::: "memory")
#define CP_WAIT2()  asm volatile("cp.async.wait_group 2;" ::: "memory")
#define CP_WAIT0()  asm volatile("cp.async.wait_group 0;" ::: "memory")

// Stage layout: 3 stages; each stage = A(128x36 floats) + B(128x36 floats)
#define ROWS_ 36
#define STAGE_F (2 * 128 * ROWS_)   // 9216 floats per stage
#define PS 132                      // epilogue pad stride (floats)
#define DYN_SMEM (3 * STAGE_F * 4)  // 110592 bytes

// ---- shared mainloop: 128x128 tile, K chunks of 32, canonical smem + cp.async ----
__device__ __forceinline__ void mma_mainloop(
    const float* __restrict__ Ab, const float* __restrict__ Bb, int Kd,
    int tid, int warp_m, int warp_n, int g, int t,
    float acc[4][4][4], float* smem)
{
    const int nCh = Kd >> 5;
    const int r_cp = tid >> 3;          // 0..31 rows per i-step (x4 steps = 128)
    const int k4_cp = (tid & 7) * 4;    // float offset within 32-float chunk

    // prologue: stages 0, 1 (nCh >= 2 always)
#pragma unroll
    for (int s = 0; s < 2; s++) {
        float* base = smem + s * STAGE_F;
        uint32_t aB = smem_u32(base), bB = smem_u32(base + 128 * ROWS_);
#pragma unroll
        for (int i = 0; i < 4; i++) {
            int r = r_cp + i * 32;
            cp16(aB + (r * ROWS_ + k4_cp) * 4, Ab + (long long)r * Kd + s * 32 + k4_cp);
            cp16(bB + (r * ROWS_ + k4_cp) * 4, Bb + (long long)r * Kd + s * 32 + k4_cp);
        }
        CP_COMMIT();
    }

    for (int c = 0; c < nCh; c++) {
        __syncthreads();                 // all warps done reading stage c-1 (buffer (c+2)%3)
        if (c + 2 < nCh) {
            float* base = smem + ((c + 2) % 3) * STAGE_F;
            uint32_t aB = smem_u32(base), bB = smem_u32(base + 128 * ROWS_);
#pragma unroll
            for (int i = 0; i < 4; i++) {
                int r = r_cp + i * 32;
                cp16(aB + (r * ROWS_ + k4_cp) * 4,
                     Ab + (long long)r * Kd + (c + 2) * 32 + k4_cp);
                cp16(bB + (r * ROWS_ + k4_cp) * 4,
                     Bb + (long long)r * Kd + (c + 2) * 32 + k4_cp);
            }
        }
        CP_COMMIT();
        CP_WAIT2();                      // stage c complete (for this thread)
        __syncthreads();                 // stage c visible to all warps

        const float* sA = smem + (c % 3) * STAGE_F;
        const float* sB = sA + 128 * ROWS_;
#pragma unroll
        for (int kf = 0; kf < 4; kf++) {
            uint32_t a[4][4], b[4][2];
            const int co = kf * 8 + t;
#pragma unroll
            for (int mi = 0; mi < 4; mi++) {
                int r = warp_m * 64 + mi * 16 + g;
                a[mi][0] = __float_as_uint(sA[r * ROWS_ + co]);
                a[mi][1] = __float_as_uint(sA[(r + 8) * ROWS_ + co]);
                a[mi][2] = __float_as_uint(sA[r * ROWS_ + co + 4]);
                a[mi][3] = __float_as_uint(sA[(r + 8) * ROWS_ + co + 4]);
            }
#pragma unroll
            for (int nf = 0; nf < 4; nf++) {
                int rb = warp_n * 32 + nf * 8 + g;
                b[nf][0] = __float_as_uint(sB[rb * ROWS_ + co]);
                b[nf][1] = __float_as_uint(sB[rb * ROWS_ + co + 4]);
            }
#pragma unroll
            for (int mi = 0; mi < 4; mi++)
#pragma unroll
                for (int nf = 0; nf < 4; nf++)
                    mma_16x8x8(acc[mi][nf], a[mi], b[nf]);
        }
    }
    CP_WAIT0();
    __syncthreads();
}

// ======== generic tf32 mma NT GEMM ========
// C  = s *(A @ Bop^T) + dI*I (+bias)   row-major [Md,Nd]
// CT = sT*(A @ Bop^T)^T + dT*I         row-major [Nd,Md]
// rc: round outputs to tf32 (for operands feeding later mma GEMMs)
__global__ __launch_bounds__(256) void gemm_mma(
    const float* __restrict__ A, const float* __restrict__ Bop,
    float* C, float* CT, const float* __restrict__ bias,
    int Kd, int ldc, int ldct,
    long long sA, long long sB, long long sC, long long sCT,
    float s, float dI, float sT, float dT, int rc)
{
    extern __shared__ float dynf[];
    const int tid = threadIdx.x;
    const int wid = tid >> 5, lane = tid & 31;
    const int warp_m = wid >> 2, warp_n = wid & 3;
    const int g = lane >> 2, t = lane & 3;
    const int m0 = blockIdx.x * 128, n0 = blockIdx.y * 128;
    const float* Ab = A + blockIdx.z * sA + (long long)m0 * Kd;
    const float* Bb = Bop + blockIdx.z * sB + (long long)n0 * Kd;

    float acc[4][4][4];
#pragma unroll
    for (int mi = 0; mi < 4; mi++)
#pragma unroll
        for (int nf = 0; nf < 4; nf++)
#pragma unroll
            for (int rr = 0; rr < 4; rr++) acc[mi][nf][rr] = 0.f;

    mma_mainloop(Ab, Bb, Kd, tid, warp_m, warp_n, g, t, acc, dynf);

    float* pad = dynf;
#pragma unroll
    for (int mi = 0; mi < 4; mi++) {
        int r0 = warp_m * 64 + mi * 16 + g;
#pragma unroll
        for (int nf = 0; nf < 4; nf++) {
            int c0 = warp_n * 32 + nf * 8 + 2 * t;
            pad[r0 * PS + c0]           = acc[mi][nf][0];
            pad[r0 * PS + c0 + 1]       = acc[mi][nf][1];
            pad[(r0 + 8) * PS + c0]     = acc[mi][nf][2];
            pad[(r0 + 8) * PS + c0 + 1] = acc[mi][nf][3];
        }
    }
    __syncthreads();

    if (C) {
        float* Cb = C + blockIdx.z * sC;
#pragma unroll
        for (int rr = 0; rr < 16; rr++) {
            int rl = rr * 8 + wid;
            int grow = m0 + rl;
            float4 v = *(float4*)(pad + rl * PS + lane * 4);
            int gc = n0 + lane * 4;
            float o[4] = {v.x, v.y, v.z, v.w};
#pragma unroll
            for (int u = 0; u < 4; u++) {
                o[u] *= s;
                if (dI != 0.f && grow == gc + u) o[u] += dI;
                if (bias) o[u] += __ldg(bias + gc + u);
                if (rc) o[u] = tf32r(o[u]);
            }
            *(float4*)(Cb + (long long)grow * ldc + gc) = make_float4(o[0], o[1], o[2], o[3]);
        }
    }
    if (CT) {
        float* CTb = CT + blockIdx.z * sCT;
#pragma unroll
        for (int rr = 0; rr < 16; rr++) {
            int cl = rr * 8 + wid;
            int gcol = n0 + cl;
            int rbase = lane * 4;
            float o[4];
#pragma unroll
            for (int u = 0; u < 4; u++) {
                float v = sT * pad[(rbase + u) * PS + cl];
                if (dT != 0.f && gcol == m0 + rbase + u) v += dT;
                if (rc) v = tf32r(v);
                o[u] = v;
            }
            *(float4*)(CTb + (long long)gcol * ldct + m0 + rbase) =
                make_float4(o[0], o[1], o[2], o[3]);
        }
    }
}

// ======== tf32 mma qkv GEMM: xr[32768,512] @ wqkvT[1536,512]^T, scatter epilogue ========
__global__ __launch_bounds__(256) void gemm_mma_qkv(
    const float* __restrict__ A, const float* __restrict__ Bop,
    float* __restrict__ Q, float* __restrict__ Kp, float* __restrict__ V)
{
    extern __shared__ float dynf[];
    const int tid = threadIdx.x;
    const int wid = tid >> 5, lane = tid & 31;
    const int warp_m = wid >> 2, warp_n = wid & 3;
    const int g = lane >> 2, t = lane & 3;
    const int m0 = blockIdx.x * 128, n0 = blockIdx.y * 128;
    const float* Ab = A + (long long)m0 * 512;
    const float* Bb = Bop + (long long)n0 * 512;

    float acc[4][4][4];
#pragma unroll
    for (int mi = 0; mi < 4; mi++)
#pragma unroll
        for (int nf = 0; nf < 4; nf++)
#pragma unroll
            for (int rr = 0; rr < 4; rr++) acc[mi][nf][rr] = 0.f;

    mma_mainloop(Ab, Bb, 512, tid, warp_m, warp_n, g, t, acc, dynf);

    float* pad = dynf;
#pragma unroll
    for (int mi = 0; mi < 4; mi++) {
        int r0 = warp_m * 64 + mi * 16 + g;
#pragma unroll
        for (int nf = 0; nf < 4; nf++) {
            int c0 = warp_n * 32 + nf * 8 + 2 * t;
            pad[r0 * PS + c0]           = acc[mi][nf][0];
            pad[r0 * PS + c0 + 1]       = acc[mi][nf][1];
            pad[(r0 + 8) * PS + c0]     = acc[mi][nf][2];
            pad[(r0 + 8) * PS + c0 + 1] = acc[mi][nf][3];
        }
    }
    __syncthreads();

    const int which = n0 >> 9;
    float* dst = (which == 0) ? Q : ((which == 1) ? Kp : V);
    const float sc = (which == 0) ? 0.125f : 1.f;
#pragma unroll
    for (int rr = 0; rr < 16; rr++) {
        int rl = rr * 8 + wid;
        int grow = m0 + rl;
        int bidx = grow >> 13, n = grow & (N_ - 1);
        int gc = n0 + lane * 4;
        int h = (gc >> 6) & 7, d = gc & 63;
        float4 v = *(float4*)(pad + rl * PS + lane * 4);
        v.x *= sc; v.y *= sc; v.z *= sc; v.w *= sc;
        long long addr = ((long long)(bidx * 8 + h) * N_ + n) * 64 + d;
        *(float4*)(dst + addr) = v;
    }
}

// ---------------- round x to tf32 (pre-pass) ----------------
__global__ __launch_bounds__(256) void round_kernel(const float* __restrict__ src,
                                                    float* __restrict__ dst, int n4)
{
    for (int i = blockIdx.x * 256 + threadIdx.x; i < n4; i += gridDim.x * 256) {
        float4 v = *(const float4*)(src + (long long)i * 4);
        v.x = tf32r(v.x); v.y = tf32r(v.y); v.z = tf32r(v.z); v.w = tf32r(v.w);
        *(float4*)(dst + (long long)i * 4) = v;
    }
}

// ---------------- weight transpose (+tf32 round): dst[C,R] = round(src[R,C]^T) --------
__global__ void transpose_kernel(const float* __restrict__ src, float* __restrict__ dst,
                                 int R, int C)
{
    __shared__ float tbuf[32][33];
    int c0 = blockIdx.x * 32, r0 = blockIdx.y * 32;
    int x = threadIdx.x, y = threadIdx.y;
#pragma unroll
    for (int i = 0; i < 32; i += 8) tbuf[y + i][x] = src[(long long)(r0 + y + i) * C + c0 + x];
    __syncthreads();
#pragma unroll
    for (int i = 0; i < 32; i += 8)
        dst[(long long)(c0 + y + i) * R + r0 + x] = tf32r(tbuf[x][y + i]);
}

// ---------------- FFMA NN GEMM (small W = Z @ A3V only) ----------------
__global__ __launch_bounds__(256) void gemm_nn(
    const float* __restrict__ A, const float* __restrict__ B,
    float* __restrict__ C, int Md, int Nd, int Kd,
    long long sA, long long sB, long long sC)
{
    A += (long long)blockIdx.z * sA;
    B += (long long)blockIdx.z * sB;
    C += (long long)blockIdx.z * sC;
    const int m0 = blockIdx.x * 128;
    const int n0 = blockIdx.y * 128;
    const int tid = threadIdx.x;
    const int tx = tid & 15, ty = tid >> 4;
    __shared__ float As[8][132];
    __shared__ float Bs[8][128];
    float acc[8][8];
#pragma unroll
    for (int i = 0; i < 8; i++)
#pragma unroll
        for (int j = 0; j < 8; j++) acc[i][j] = 0.f;
    const int ar = tid >> 1, ac = (tid & 1) * 4;
    const int bk = tid >> 5, bn = (tid & 31) * 4;
    const bool bok = (n0 + bn < Nd);
    for (int kk = 0; kk < Kd; kk += 8) {
        float4 av = *(const float4*)(A + (long long)(m0 + ar) * Kd + kk + ac);
        float4 bv = make_float4(0.f, 0.f, 0.f, 0.f);
        if (bok) bv = *(const float4*)(B + (long long)(kk + bk) * Nd + n0 + bn);
        As[ac + 0][ar] = av.x; As[ac + 1][ar] = av.y;
        As[ac + 2][ar] = av.z; As[ac + 3][ar] = av.w;
        *(float4*)&Bs[bk][bn] = bv;
        __syncthreads();
#pragma unroll
        for (int k = 0; k < 8; k++) {
            float a[8], b[8];
            *(float4*)&a[0] = *(const float4*)&As[k][ty * 8];
            *(float4*)&a[4] = *(const float4*)&As[k][ty * 8 + 4];
            *(float4*)&b[0] = *(const float4*)&Bs[k][tx * 8];
            *(float4*)&b[4] = *(const float4*)&Bs[k][tx * 8 + 4];
#pragma unroll
            for (int i = 0; i < 8; i++)
#pragma unroll
                for (int j = 0; j < 8; j++)
                    acc[i][j] = fmaf(a[i], b[j], acc[i][j]);
        }
        __syncthreads();
    }
#pragma unroll
    for (int i = 0; i < 8; i++) {
        int row = m0 + ty * 8 + i;
        if (row >= Md) continue;
#pragma unroll
        for (int jg = 0; jg < 8; jg += 4) {
            int col = n0 + tx * 8 + jg;
            if (col >= Nd) continue;
            float4 o = make_float4(acc[i][jg], acc[i][jg + 1], acc[i][jg + 2], acc[i][jg + 3]);
            *(float4*)(C + (long long)row * Nd + col) = o;
        }
    }
}

// ---------------- fused online-softmax attention: Out = softmax(A @ B^T) @ V ----------
__global__ __launch_bounds__(256) void fused_attn(
    const float* __restrict__ Arows, const float* __restrict__ Bmat,
    const float* __restrict__ Vmat, float* __restrict__ Out,
    int nChunks, long long sA, long long sB, long long sO)
{
    const int bh = blockIdx.y;
    const int row0 = blockIdx.x * 64;
    const float* Ab = Arows + (long long)bh * sA + (long long)row0 * 64;
    const float* Bb = Bmat + (long long)bh * sB;
    const float* Vb = Vmat + (long long)bh * sB;
    float* Ob = Out + (long long)bh * sO + (long long)row0 * 64;

    __shared__ float As[64][68];
    __shared__ float Kc[32][68];
    __shared__ float Vc[32][68];
    __shared__ float P[64][36];

    const int tid = threadIdx.x;
    const int r = tid >> 2;
    const int cg = tid & 3;
#pragma unroll
    for (int k = 0; k < 4; k++) {
        int f = tid + k * 256;
        int rr = f >> 4, c4 = (f & 15) * 4;
        *(float4*)&As[rr][c4] = *(const float4*)(Ab + (long long)rr * 64 + c4);
    }
    float acc[16];
#pragma unroll
    for (int i = 0; i < 16; i++) acc[i] = 0.f;
    float mrun = -3.0e38f, srun = 0.f;

    for (int ch = 0; ch < nChunks; ch++) {
        const float* Kg = Bb + (long long)ch * 32 * 64;
        const float* Vg = Vb + (long long)ch * 32 * 64;
#pragma unroll
        for (int k = 0; k < 2; k++) {
            int f = tid + k * 256;
            int jj = f >> 4, c4 = (f & 15) * 4;
            *(float4*)&Kc[jj][c4] = *(const float4*)(Kg + jj * 64 + c4);
            *(float4*)&Vc[jj][c4] = *(const float4*)(Vg + jj * 64 + c4);
        }
        __syncthreads();
        float s[8];
#pragma unroll
        for (int jj = 0; jj < 8; jj++) s[jj] = 0.f;
#pragma unroll
        for (int d4 = 0; d4 < 64; d4 += 4) {
            float4 a4 = *(float4*)&As[r][d4];
#pragma unroll
            for (int jj = 0; jj < 8; jj++) {
                float4 k4 = *(float4*)&Kc[cg * 8 + jj][d4];
                s[jj] += a4.x * k4.x + a4.y * k4.y + a4.z * k4.z + a4.w * k4.w;
            }
        }
        float mloc = s[0];
#pragma unroll
        for (int jj = 1; jj < 8; jj++) mloc = fmaxf(mloc, s[jj]);
        mloc = fmaxf(mloc, __shfl_xor_sync(0xffffffffu, mloc, 1));
        mloc = fmaxf(mloc, __shfl_xor_sync(0xffffffffu, mloc, 2));
        float mnew = fmaxf(mrun, mloc);
        float corr = __expf(mrun - mnew);
        float sl = 0.f;
#pragma unroll
        for (int jj = 0; jj < 8; jj++) {
            float p = __expf(s[jj] - mnew);
            P[r][cg * 8 + jj] = p;
            sl += p;
        }
        sl += __shfl_xor_sync(0xffffffffu, sl, 1);
        sl += __shfl_xor_sync(0xffffffffu, sl, 2);
        srun = srun * corr + sl;
#pragma unroll
        for (int i = 0; i < 16; i++) acc[i] *= corr;
        mrun = mnew;
        __syncwarp();
#pragma unroll 4
        for (int j = 0; j < 32; j++) {
            float p = P[r][j];
            float4 v0 = *(float4*)&Vc[j][cg * 16];
            float4 v1 = *(float4*)&Vc[j][cg * 16 + 4];
            float4 v2 = *(float4*)&Vc[j][cg * 16 + 8];
            float4 v3 = *(float4*)&Vc[j][cg * 16 + 12];
            acc[0]  = fmaf(p, v0.x, acc[0]);  acc[1]  = fmaf(p, v0.y, acc[1]);
            acc[2]  = fmaf(p, v0.z, acc[2]);  acc[3]  = fmaf(p, v0.w, acc[3]);
            acc[4]  = fmaf(p, v1.x, acc[4]);  acc[5]  = fmaf(p, v1.y, acc[5]);
            acc[6]  = fmaf(p, v1.z, acc[6]);  acc[7]  = fmaf(p, v1.w, acc[7]);
            acc[8]  = fmaf(p, v2.x, acc[8]);  acc[9]  = fmaf(p, v2.y, acc[9]);
            acc[10] = fmaf(p, v2.z, acc[10]); acc[11] = fmaf(p, v2.w, acc[11]);
            acc[12] = fmaf(p, v3.x, acc[12]); acc[13] = fmaf(p, v3.y, acc[13]);
            acc[14] = fmaf(p, v3.z, acc[14]); acc[15] = fmaf(p, v3.w, acc[15]);
        }
        __syncthreads();
    }
    float inv = 1.f / srun;
    float* po = Ob + (long long)r * 64 + cg * 16;
#pragma unroll
    for (int gg = 0; gg < 4; gg++) {
        float4 o = make_float4(acc[gg * 4] * inv, acc[gg * 4 + 1] * inv,
                               acc[gg * 4 + 2] * inv, acc[gg * 4 + 3] * inv);
        *(float4*)(po + gg * 4) = o;
    }
}

// ---------------- landmark means (+tf32 round, feeds mma) ----------------
__global__ void landmark_kernel(const float* __restrict__ src, float* __restrict__ dst)
{
    int m = blockIdx.x, bh = blockIdx.y, d = threadIdx.x;
    const float* p = src + ((long long)bh * N_ + (long long)m * L_) * DH_ + d;
    float s = 0.f;
#pragma unroll
    for (int i = 0; i < L_; i++) s += p[i * DH_];
    dst[((long long)bh * M_ + m) * DH_ + d] = tf32r(s * (1.f / (float)L_));
}

__device__ __forceinline__ float warpMaxRed(float v) {
#pragma unroll
    for (int o = 16; o; o >>= 1) v = fmaxf(v, __shfl_xor_sync(0xffffffffu, v, o));
    return v;
}
__device__ __forceinline__ float warpSumRed(float v) {
#pragma unroll
    for (int o = 16; o; o >>= 1) v += __shfl_xor_sync(0xffffffffu, v, o);
    return v;
}

// softmax over 256-wide rows (+tf32 round, feeds pinv mma chain)
__global__ __launch_bounds__(256) void softmax_rows256(float* __restrict__ A)
{
    int warp = threadIdx.x >> 5, lane = threadIdx.x & 31;
    long long row = (long long)blockIdx.x * 8 + warp;
    float* p = A + row * 256;
    float4 v0 = *(float4*)(p + lane * 8);
    float4 v1 = *(float4*)(p + lane * 8 + 4);
    float mx = fmaxf(fmaxf(fmaxf(v0.x, v0.y), fmaxf(v0.z, v0.w)),
                     fmaxf(fmaxf(v1.x, v1.y), fmaxf(v1.z, v1.w)));
    mx = warpMaxRed(mx);
    v0.x = __expf(v0.x - mx); v0.y = __expf(v0.y - mx);
    v0.z = __expf(v0.z - mx); v0.w = __expf(v0.w - mx);
    v1.x = __expf(v1.x - mx); v1.y = __expf(v1.y - mx);
    v1.z = __expf(v1.z - mx); v1.w = __expf(v1.w - mx);
    float sm = v0.x + v0.y + v0.z + v0.w + v1.x + v1.y + v1.z + v1.w;
    sm = warpSumRed(sm);
    float inv = 1.f / sm;
    v0.x = tf32r(v0.x * inv); v0.y = tf32r(v0.y * inv);
    v0.z = tf32r(v0.z * inv); v0.w = tf32r(v0.w * inv);
    v1.x = tf32r(v1.x * inv); v1.y = tf32r(v1.y * inv);
    v1.z = tf32r(v1.z * inv); v1.w = tf32r(v1.w * inv);
    *(float4*)(p + lane * 8) = v0;
    *(float4*)(p + lane * 8 + 4) = v1;
}

// ---------------- pinv support ----------------
__global__ void init_max_kernel() { gMaxBits = 0; }

__global__ __launch_bounds__(256) void colmax_kernel(const float* __restrict__ A2)
{
    int bh = blockIdx.x, j = threadIdx.x;
    const float* p = A2 + ((long long)bh << 16) + j;
    float s = 0.f;
#pragma unroll 8
    for (int i = 0; i < 256; i++) s += p[i << 8];
    atomicMax(&gMaxBits, __float_as_int(s));
}

__global__ __launch_bounds__(256) void zinit_kernel(const float* __restrict__ A2,
                                                    float* __restrict__ Z,
                                                    float* __restrict__ ZT)
{
    int idx = blockIdx.x * 256 + threadIdx.x;
    float inv = 1.f / __int_as_float(gMaxBits);
    int bh = idx >> 16, r = idx & 65535, i = r >> 8, j = r & 255;
    Z[idx]  = tf32r(A2[(bh << 16) + (j << 8) + i] * inv);
    ZT[idx] = tf32r(A2[idx] * inv);
}

// ---------------- depthwise conv(k=33) + add + concat heads (+tf32 round) ----------
__global__ __launch_bounds__(256) void convcat_kernel(
    const float* __restrict__ V, const float* __restrict__ OH,
    const float* __restrict__ ker, float* __restrict__ CAT)
{
    int b = blockIdx.z, h = blockIdx.y, n0 = blockIdx.x * 64;
    int bh = b * H_ + h;
    __shared__ float sV[96][64];
    __shared__ float kw[33];
    int t = threadIdx.x;
    if (t < 33) kw[t] = ker[h * 33 + t];
    const float* Vb = V + (long long)bh * N_ * DH_;
    for (int idx = t; idx < 96 * 16; idx += 256) {
        int r = idx >> 4;
        int c4 = (idx & 15) * 4;
        int n = n0 - 16 + r;
        float4 val = make_float4(0.f, 0.f, 0.f, 0.f);
        if (n >= 0 && n < N_) val = *(const float4*)(Vb + (long long)n * DH_ + c4);
        *(float4*)&sV[r][c4] = val;
    }
    __syncthreads();
    int d = t & 63, nl0 = t >> 6;
#pragma unroll
    for (int ii = 0; ii < 16; ii++) {
        int nl = nl0 + ii * 4;
        float acc = 0.f;
#pragma unroll
        for (int tt = 0; tt < 33; tt++) acc = fmaf(sV[nl + tt][d], kw[tt], acc);
        int n = n0 + nl;
        float o = OH[((long long)bh * N_ + n) * DH_ + d] + acc;
        CAT[((long long)(b * N_ + n)) * 512 + h * 64 + d] = tf32r(o);
    }
}

// ---------------- host ----------------
extern "C" void kernel_launch(void* const* d_in, const int* in_sizes, int n_in,
                              void* d_out, int out_size)
{
    const float* x     = (const float*)d_in[0];
    const float* wqkv  = (const float*)d_in[1];
    const float* wout  = (const float*)d_in[2];
    const float* bout  = (const float*)d_in[3];
    const float* rker  = (const float*)d_in[4];
    float* out = (float*)d_out;

    cudaFuncSetAttribute(gemm_mma, cudaFuncAttributeMaxDynamicSharedMemorySize, DYN_SMEM);
    cudaFuncSetAttribute(gemm_mma_qkv, cudaFuncAttributeMaxDynamicSharedMemorySize, DYN_SMEM);

    float *pQ, *pK, *pV, *pQL, *pKL, *pA2, *pZ, *pZT, *pZ2, *pZ2T, *pX;
    float *pT1, *pT2, *pA3V, *pW, *pOH, *pCAT, *pWqkvT, *pWoutT;
    cudaGetSymbolAddress((void**)&pQ,  gQ);
    cudaGetSymbolAddress((void**)&pK,  gK);
    cudaGetSymbolAddress((void**)&pV,  gV);
    cudaGetSymbolAddress((void**)&pQL, gQL);
    cudaGetSymbolAddress((void**)&pKL, gKL);
    cudaGetSymbolAddress((void**)&pA2, gA2);
    cudaGetSymbolAddress((void**)&pZ,  gZ);
    cudaGetSymbolAddress((void**)&pZT, gZT);
    cudaGetSymbolAddress((void**)&pZ2, gZ2);
    cudaGetSymbolAddress((void**)&pZ2T, gZ2T);
    cudaGetSymbolAddress((void**)&pX,  gX);
    cudaGetSymbolAddress((void**)&pT1, gT1);
    cudaGetSymbolAddress((void**)&pT2, gT2);
    cudaGetSymbolAddress((void**)&pA3V, gA3V);
    cudaGetSymbolAddress((void**)&pW,  gW);
    cudaGetSymbolAddress((void**)&pOH, gOH);
    cudaGetSymbolAddress((void**)&pCAT, gCAT);
    cudaGetSymbolAddress((void**)&pWqkvT, gWqkvT);
    cudaGetSymbolAddress((void**)&pWoutT, gWoutT);

    const long long MM = (long long)M_ * M_;
    const long long MD = (long long)M_ * DH_;
    const long long ND = (long long)N_ * DH_;

    // 0) tf32-round x into gCAT (reused later by convcat); transpose+round weights
    round_kernel<<<4096, 256>>>(x, pCAT, 4194304);
    transpose_kernel<<<dim3(48, 16), dim3(32, 8)>>>(wqkv, pWqkvT, 512, 1536);
    transpose_kernel<<<dim3(16, 16), dim3(32, 8)>>>(wout, pWoutT, 512, 512);
    // 1) qkv GEMM with scatter epilogue (reads rounded x)
    gemm_mma_qkv<<<dim3(256, 12), 256, DYN_SMEM>>>(pCAT, pWqkvT, pQ, pK, pV);
    // 2) landmarks (rounded outputs)
    landmark_kernel<<<dim3(M_, BH_), DH_>>>(pQ, pQL);
    landmark_kernel<<<dim3(M_, BH_), DH_>>>(pK, pKL);
    // 3) attn2 = softmax(QL @ KL^T)
    gemm_mma<<<dim3(2, 2, BH_), 256, DYN_SMEM>>>(pQL, pKL, pA2, nullptr, nullptr,
                                                 64, 256, 0, MD, MD, MM, 0,
                                                 1.f, 0.f, 0.f, 0.f, 0);
    softmax_rows256<<<1024, 256>>>(pA2);
    // 4) pinv init
    init_max_kernel<<<1, 1>>>();
    colmax_kernel<<<BH_, 256>>>(pA2);
    zinit_kernel<<<8192, 256>>>(pA2, pZ, pZT);
    // 5) Newton-Schulz iterations (all operands tf32-rounded)
    float *zin = pZ, *zinT = pZT, *zout = pZ2, *zoutT = pZ2T;
    for (int it = 0; it < 6; it++) {
        gemm_mma<<<dim3(2, 2, BH_), 256, DYN_SMEM>>>(pA2, zinT, pX, pT1, nullptr,
                                                     256, 256, 256, MM, MM, MM, MM,
                                                     1.f, 0.f, -1.f, 7.f, 1);
        gemm_mma<<<dim3(2, 2, BH_), 256, DYN_SMEM>>>(pX, pT1, nullptr, pT2, nullptr,
                                                     256, 256, 256, MM, MM, MM, MM,
                                                     0.f, 0.f, -1.f, 15.f, 1);
        gemm_mma<<<dim3(2, 2, BH_), 256, DYN_SMEM>>>(pX, pT2, nullptr, pT1, nullptr,
                                                     256, 256, 256, MM, MM, MM, MM,
                                                     0.f, 0.f, -1.f, 13.f, 1);
        gemm_mma<<<dim3(2, 2, BH_), 256, DYN_SMEM>>>(zin, pT1, zout, zoutT, nullptr,
                                                     256, 256, 256, MM, MM, MM, MM,
                                                     0.25f, 0.f, 0.25f, 0.f, 1);
        float* t;
        t = zin; zin = zout; zout = t;
        t = zinT; zinT = zoutT; zoutT = t;
    }
    // 6) A3V = softmax(QL @ K^T) @ V (fused, FFMA)
    fused_attn<<<dim3(4, BH_), 256>>>(pQL, pK, pV, pA3V, N_ / 32, MD, ND, MD);
    // 7) W = Zfinal @ A3V (small FFMA NN)
    gemm_nn<<<dim3(2, 1, BH_), 256>>>(zin, pA3V, pW, 256, 64, 256, MM, MD, MD);
    // 8) OH = softmax(Q @ KL^T) @ W (fused, FFMA)
    fused_attn<<<dim3(128, BH_), 256>>>(pQ, pKL, pW, pOH, M_ / 32, ND, MD, ND);
    // 9) conv + concat (rounded CAT)
    convcat_kernel<<<dim3(128, H_, B_), 256>>>(pV, pOH, rker, pCAT);
    // 10) out = CAT @ wout + bout
    gemm_mma<<<dim3(256, 4), 256, DYN_SMEM>>>(pCAT, pWoutT, out, nullptr, bout,
                                              512, 512, 0, 0, 0, 0, 0,
                                              1.f, 0.f, 0.f, 0.f, 0);
}

// round 8
// speedup vs baseline: 5.9464x; 4.7124x over previous
#include <cuda_runtime.h>
#include <cstdint>
#include <math.h>

// Problem constants
#define B_   4
#define H_   8
#define N_   8192
#define DH_  64
#define M_   256
#define L_   32
#define BH_  32

// ---------------- scratch (device globals; no allocation anywhere) ----------------
__device__ float gQ[16777216];     // [BH,N,DH] (pre-scaled, tf32-rounded)
__device__ float gK[16777216];
__device__ float gV[16777216];
__device__ float gQL[524288];      // [BH,M,DH]
__device__ float gKL[524288];
__device__ float gA2[2097152];     // [BH,M,M] softmaxed (tf32-rounded)
__device__ float gZ [2097152];
__device__ float gZT[2097152];
__device__ float gZ2[2097152];
__device__ float gZ2T[2097152];
__device__ float gX [2097152];
__device__ float gT1[2097152];     // U1T / U3T
__device__ float gT2[2097152];     // U2T
__device__ float gA3V[524288];
__device__ float gW [524288];
__device__ float gOH[16777216];
__device__ float gCAT[16777216];   // rounded-x first, then conv output
__device__ float gWqkvT[786432];   // [1536,512]
__device__ float gWoutT[262144];   // [512,512]
__device__ int   gMaxBits;

// ================= helpers =================
__device__ __forceinline__ uint32_t smem_u32(const void* p) {
    uint32_t a;
    asm("{ .reg .u64 t; cvta.to.shared.u64 t, %1; cvt.u32.u64 %0, t; }" : "=r"(a) : "l"(p));
    return a;
}
__device__ __forceinline__ float tf32r(float v) {
    uint32_t u;
    asm("cvt.rna.tf32.f32 %0, %1;" : "=r"(u) : "f"(v));
    return __uint_as_float(u);
}
__device__ __forceinline__ void mma_16x8x8(float* c, const uint32_t* a, const uint32_t* b) {
    asm volatile("mma.sync.aligned.m16n8k8.row.col.f32.tf32.tf32.f32 "
                 "{%0,%1,%2,%3}, {%4,%5,%6,%7}, {%8,%9}, {%0,%1,%2,%3};"
                 : "+f"(c[0]), "+f"(c[1]), "+f"(c[2]), "+f"(c[3])
                 : "r"(a[0]), "r"(a[1]), "r"(a[2]), "r"(a[3]), "r"(b[0]), "r"(b[1]));
}
__device__ __forceinline__ void cp16(uint32_t dst, const float* src) {
    asm volatile("cp.async.cg.shared.global [%0], [%1], 16;" :: "r"(dst), "l"(src) : "memory");
}
#define CP_COMMIT() asm volatile("cp.async.commit_group;" ::: "memory")
#define CP_WAIT2()  asm volatile("cp.async.wait_group 2;" ::: "memory")
#define CP_WAIT1()  asm volatile("cp.async.wait_group 1;" ::: "memory")
#define CP_WAIT0()  asm volatile("cp.async.wait_group 0;" ::: "memory")

// Stage layout for GEMM: 3 stages; each stage = A(128x36 floats) + B(128x36 floats)
#define ROWS_ 36
#define STAGE_F (2 * 128 * ROWS_)
#define PS 132
#define DYN_SMEM (3 * STAGE_F * 4)

// ---- shared GEMM mainloop: 128x128 tile, K chunks of 32, canonical smem + cp.async ----
__device__ __forceinline__ void mma_mainloop(
    const float* __restrict__ Ab, const float* __restrict__ Bb, int Kd,
    int tid, int warp_m, int warp_n, int g, int t,
    float acc[4][4][4], float* smem)
{
    const int nCh = Kd >> 5;
    const int r_cp = tid >> 3;
    const int k4_cp = (tid & 7) * 4;

#pragma unroll
    for (int s = 0; s < 2; s++) {
        float* base = smem + s * STAGE_F;
        uint32_t aB = smem_u32(base), bB = smem_u32(base + 128 * ROWS_);
#pragma unroll
        for (int i = 0; i < 4; i++) {
            int r = r_cp + i * 32;
            cp16(aB + (r * ROWS_ + k4_cp) * 4, Ab + (long long)r * Kd + s * 32 + k4_cp);
            cp16(bB + (r * ROWS_ + k4_cp) * 4, Bb + (long long)r * Kd + s * 32 + k4_cp);
        }
        CP_COMMIT();
    }

    for (int c = 0; c < nCh; c++) {
        __syncthreads();
        if (c + 2 < nCh) {
            float* base = smem + ((c + 2) % 3) * STAGE_F;
            uint32_t aB = smem_u32(base), bB = smem_u32(base + 128 * ROWS_);
#pragma unroll
            for (int i = 0; i < 4; i++) {
                int r = r_cp + i * 32;
                cp16(aB + (r * ROWS_ + k4_cp) * 4,
                     Ab + (long long)r * Kd + (c + 2) * 32 + k4_cp);
                cp16(bB + (r * ROWS_ + k4_cp) * 4,
                     Bb + (long long)r * Kd + (c + 2) * 32 + k4_cp);
            }
        }
        CP_COMMIT();
        CP_WAIT2();
        __syncthreads();

        const float* sA = smem + (c % 3) * STAGE_F;
        const float* sB = sA + 128 * ROWS_;
#pragma unroll
        for (int kf = 0; kf < 4; kf++) {
            uint32_t a[4][4], b[4][2];
            const int co = kf * 8 + t;
#pragma unroll
            for (int mi = 0; mi < 4; mi++) {
                int r = warp_m * 64 + mi * 16 + g;
                a[mi][0] = __float_as_uint(sA[r * ROWS_ + co]);
                a[mi][1] = __float_as_uint(sA[(r + 8) * ROWS_ + co]);
                a[mi][2] = __float_as_uint(sA[r * ROWS_ + co + 4]);
                a[mi][3] = __float_as_uint(sA[(r + 8) * ROWS_ + co + 4]);
            }
#pragma unroll
            for (int nf = 0; nf < 4; nf++) {
                int rb = warp_n * 32 + nf * 8 + g;
                b[nf][0] = __float_as_uint(sB[rb * ROWS_ + co]);
                b[nf][1] = __float_as_uint(sB[rb * ROWS_ + co + 4]);
            }
#pragma unroll
            for (int mi = 0; mi < 4; mi++)
#pragma unroll
                for (int nf = 0; nf < 4; nf++)
                    mma_16x8x8(acc[mi][nf], a[mi], b[nf]);
        }
    }
    CP_WAIT0();
    __syncthreads();
}

// ======== generic tf32 mma NT GEMM ========
__global__ __launch_bounds__(256) void gemm_mma(
    const float* __restrict__ A, const float* __restrict__ Bop,
    float* C, float* CT, const float* __restrict__ bias,
    int Kd, int ldc, int ldct,
    long long sA, long long sB, long long sC, long long sCT,
    float s, float dI, float sT, float dT, int rc)
{
    extern __shared__ float dynf[];
    const int tid = threadIdx.x;
    const int wid = tid >> 5, lane = tid & 31;
    const int warp_m = wid >> 2, warp_n = wid & 3;
    const int g = lane >> 2, t = lane & 3;
    const int m0 = blockIdx.x * 128, n0 = blockIdx.y * 128;
    const float* Ab = A + blockIdx.z * sA + (long long)m0 * Kd;
    const float* Bb = Bop + blockIdx.z * sB + (long long)n0 * Kd;

    float acc[4][4][4];
#pragma unroll
    for (int mi = 0; mi < 4; mi++)
#pragma unroll
        for (int nf = 0; nf < 4; nf++)
#pragma unroll
            for (int rr = 0; rr < 4; rr++) acc[mi][nf][rr] = 0.f;

    mma_mainloop(Ab, Bb, Kd, tid, warp_m, warp_n, g, t, acc, dynf);

    float* pad = dynf;
#pragma unroll
    for (int mi = 0; mi < 4; mi++) {
        int r0 = warp_m * 64 + mi * 16 + g;
#pragma unroll
        for (int nf = 0; nf < 4; nf++) {
            int c0 = warp_n * 32 + nf * 8 + 2 * t;
            pad[r0 * PS + c0]           = acc[mi][nf][0];
            pad[r0 * PS + c0 + 1]       = acc[mi][nf][1];
            pad[(r0 + 8) * PS + c0]     = acc[mi][nf][2];
            pad[(r0 + 8) * PS + c0 + 1] = acc[mi][nf][3];
        }
    }
    __syncthreads();

    if (C) {
        float* Cb = C + blockIdx.z * sC;
#pragma unroll
        for (int rr = 0; rr < 16; rr++) {
            int rl = rr * 8 + wid;
            int grow = m0 + rl;
            float4 v = *(float4*)(pad + rl * PS + lane * 4);
            int gc = n0 + lane * 4;
            float o[4] = {v.x, v.y, v.z, v.w};
#pragma unroll
            for (int u = 0; u < 4; u++) {
                o[u] *= s;
                if (dI != 0.f && grow == gc + u) o[u] += dI;
                if (bias) o[u] += __ldg(bias + gc + u);
                if (rc) o[u] = tf32r(o[u]);
            }
            *(float4*)(Cb + (long long)grow * ldc + gc) = make_float4(o[0], o[1], o[2], o[3]);
        }
    }
    if (CT) {
        float* CTb = CT + blockIdx.z * sCT;
#pragma unroll
        for (int rr = 0; rr < 16; rr++) {
            int cl = rr * 8 + wid;
            int gcol = n0 + cl;
            int rbase = lane * 4;
            float o[4];
#pragma unroll
            for (int u = 0; u < 4; u++) {
                float v = sT * pad[(rbase + u) * PS + cl];
                if (dT != 0.f && gcol == m0 + rbase + u) v += dT;
                if (rc) v = tf32r(v);
                o[u] = v;
            }
            *(float4*)(CTb + (long long)gcol * ldct + m0 + rbase) =
                make_float4(o[0], o[1], o[2], o[3]);
        }
    }
}

// ======== tf32 mma qkv GEMM: scatter epilogue, outputs tf32-rounded ========
__global__ __launch_bounds__(256) void gemm_mma_qkv(
    const float* __restrict__ A, const float* __restrict__ Bop,
    float* __restrict__ Q, float* __restrict__ Kp, float* __restrict__ V)
{
    extern __shared__ float dynf[];
    const int tid = threadIdx.x;
    const int wid = tid >> 5, lane = tid & 31;
    const int warp_m = wid >> 2, warp_n = wid & 3;
    const int g = lane >> 2, t = lane & 3;
    const int m0 = blockIdx.x * 128, n0 = blockIdx.y * 128;
    const float* Ab = A + (long long)m0 * 512;
    const float* Bb = Bop + (long long)n0 * 512;

    float acc[4][4][4];
#pragma unroll
    for (int mi = 0; mi < 4; mi++)
#pragma unroll
        for (int nf = 0; nf < 4; nf++)
#pragma unroll
            for (int rr = 0; rr < 4; rr++) acc[mi][nf][rr] = 0.f;

    mma_mainloop(Ab, Bb, 512, tid, warp_m, warp_n, g, t, acc, dynf);

    float* pad = dynf;
#pragma unroll
    for (int mi = 0; mi < 4; mi++) {
        int r0 = warp_m * 64 + mi * 16 + g;
#pragma unroll
        for (int nf = 0; nf < 4; nf++) {
            int c0 = warp_n * 32 + nf * 8 + 2 * t;
            pad[r0 * PS + c0]           = acc[mi][nf][0];
            pad[r0 * PS + c0 + 1]       = acc[mi][nf][1];
            pad[(r0 + 8) * PS + c0]     = acc[mi][nf][2];
            pad[(r0 + 8) * PS + c0 + 1] = acc[mi][nf][3];
        }
    }
    __syncthreads();

    const int which = n0 >> 9;
    float* dst = (which == 0) ? Q : ((which == 1) ? Kp : V);
    const float sc = (which == 0) ? 0.125f : 1.f;
#pragma unroll
    for (int rr = 0; rr < 16; rr++) {
        int rl = rr * 8 + wid;
        int grow = m0 + rl;
        int bidx = grow >> 13, n = grow & (N_ - 1);
        int gc = n0 + lane * 4;
        int h = (gc >> 6) & 7, d = gc & 63;
        float4 v = *(float4*)(pad + rl * PS + lane * 4);
        v.x = tf32r(v.x * sc); v.y = tf32r(v.y * sc);
        v.z = tf32r(v.z * sc); v.w = tf32r(v.w * sc);
        long long addr = ((long long)(bidx * 8 + h) * N_ + n) * 64 + d;
        *(float4*)(dst + addr) = v;
    }
}

// ======== fused flash attention on tensor cores: Out = softmax(A @ B^T) @ V ========
// A: [rows][64] per bh (tf32); B,V: [nChunks*64][64] (tf32); Out: [rows][64]
#define AST 68
#define DYN_ATTN ((6 * 64 * AST + 64) * 4)

__global__ __launch_bounds__(256) void fused_attn_mma(
    const float* __restrict__ Arows, const float* __restrict__ Bmat,
    const float* __restrict__ Vmat, float* __restrict__ Out,
    int nChunks, long long sA, long long sB, long long sO)
{
    extern __shared__ float dynf[];
    float* sAq = dynf;                 // [64][AST]
    float* sKb[2] = {sAq + 64 * AST, sAq + 2 * 64 * AST};
    float* sVb[2] = {sAq + 3 * 64 * AST, sAq + 4 * 64 * AST};
    float* sP  = sAq + 5 * 64 * AST;   // [64][AST]
    float* sCr = sP + 64 * AST;        // [64]

    const int tid = threadIdx.x;
    const int wid = tid >> 5, lane = tid & 31;
    const int warp_m = wid >> 2, warp_n = wid & 3;
    const int g = lane >> 2, t = lane & 3;
    const int bh = blockIdx.y;
    const int row0 = blockIdx.x * 64;
    const float* Ab = Arows + bh * sA + (long long)row0 * 64;
    const float* Bb = Bmat + bh * sB;
    const float* Vb = Vmat + bh * sB;
    float* Ob = Out + bh * sO + (long long)row0 * 64;

    // load A tile
#pragma unroll
    for (int i = 0; i < 4; i++) {
        int f = tid + i * 256;
        int r = f >> 4, c4 = (f & 15) * 4;
        *(float4*)&sAq[r * AST + c4] = *(const float4*)(Ab + (long long)r * 64 + c4);
    }

    // prologue: chunk 0 (64 rows x 64 cols)
    {
        uint32_t dk = smem_u32(sKb[0]), dv = smem_u32(sVb[0]);
#pragma unroll
        for (int i = 0; i < 4; i++) {
            int gk = tid + i * 256;
            int r = gk >> 4, cc = (gk & 15) * 4;
            cp16(dk + (r * AST + cc) * 4, Bb + (long long)r * 64 + cc);
            cp16(dv + (r * AST + cc) * 4, Vb + (long long)r * 64 + cc);
        }
        CP_COMMIT();
    }

    float acc_o[2][2][4];
#pragma unroll
    for (int mi = 0; mi < 2; mi++)
#pragma unroll
        for (int nf = 0; nf < 2; nf++)
#pragma unroll
            for (int rr = 0; rr < 4; rr++) acc_o[mi][nf][rr] = 0.f;

    const int sr = tid >> 2;
    const int cg = tid & 3;
    float mrun = -3.0e38f, srun = 0.f;

    for (int c = 0; c < nChunks; c++) {
        if (c + 1 < nChunks) {
            uint32_t dk = smem_u32(sKb[(c + 1) & 1]);
            uint32_t dv = smem_u32(sVb[(c + 1) & 1]);
            const float* Kg = Bb + (long long)(c + 1) * 64 * 64;
            const float* Vg = Vb + (long long)(c + 1) * 64 * 64;
#pragma unroll
            for (int i = 0; i < 4; i++) {
                int gk = tid + i * 256;
                int r = gk >> 4, cc = (gk & 15) * 4;
                cp16(dk + (r * AST + cc) * 4, Kg + (long long)r * 64 + cc);
                cp16(dv + (r * AST + cc) * 4, Vg + (long long)r * 64 + cc);
            }
        }
        CP_COMMIT();
        CP_WAIT1();
        __syncthreads();

        const float* cK = sKb[c & 1];
        const float* cV = sVb[c & 1];

        // S = A @ K^T
        float acc_s[2][2][4];
#pragma unroll
        for (int mi = 0; mi < 2; mi++)
#pragma unroll
            for (int nf = 0; nf < 2; nf++)
#pragma unroll
                for (int rr = 0; rr < 4; rr++) acc_s[mi][nf][rr] = 0.f;
#pragma unroll
        for (int kf = 0; kf < 8; kf++) {
            const int co = kf * 8 + t;
            uint32_t a[2][4], b[2][2];
#pragma unroll
            for (int mi = 0; mi < 2; mi++) {
                int r = warp_m * 32 + mi * 16 + g;
                a[mi][0] = __float_as_uint(sAq[r * AST + co]);
                a[mi][1] = __float_as_uint(sAq[(r + 8) * AST + co]);
                a[mi][2] = __float_as_uint(sAq[r * AST + co + 4]);
                a[mi][3] = __float_as_uint(sAq[(r + 8) * AST + co + 4]);
            }
#pragma unroll
            for (int nf = 0; nf < 2; nf++) {
                int rb = warp_n * 16 + nf * 8 + g;
                b[nf][0] = __float_as_uint(cK[rb * AST + co]);
                b[nf][1] = __float_as_uint(cK[rb * AST + co + 4]);
            }
#pragma unroll
            for (int mi = 0; mi < 2; mi++)
#pragma unroll
                for (int nf = 0; nf < 2; nf++)
                    mma_16x8x8(acc_s[mi][nf], a[mi], b[nf]);
        }
        // store S frags
#pragma unroll
        for (int mi = 0; mi < 2; mi++) {
            int r0 = warp_m * 32 + mi * 16 + g;
#pragma unroll
            for (int nf = 0; nf < 2; nf++) {
                int c0 = warp_n * 16 + nf * 8 + 2 * t;
                sP[r0 * AST + c0]           = acc_s[mi][nf][0];
                sP[r0 * AST + c0 + 1]       = acc_s[mi][nf][1];
                sP[(r0 + 8) * AST + c0]     = acc_s[mi][nf][2];
                sP[(r0 + 8) * AST + c0 + 1] = acc_s[mi][nf][3];
            }
        }
        __syncthreads();

        // softmax over this 64-col chunk
        float v[16];
#pragma unroll
        for (int q = 0; q < 4; q++)
            *(float4*)&v[q * 4] = *(float4*)&sP[sr * AST + cg * 16 + q * 4];
        float mloc = v[0];
#pragma unroll
        for (int j = 1; j < 16; j++) mloc = fmaxf(mloc, v[j]);
        mloc = fmaxf(mloc, __shfl_xor_sync(0xffffffffu, mloc, 1));
        mloc = fmaxf(mloc, __shfl_xor_sync(0xffffffffu, mloc, 2));
        float mnew = fmaxf(mrun, mloc);
        float corr = __expf(mrun - mnew);
        float sl = 0.f;
#pragma unroll
        for (int j = 0; j < 16; j++) {
            float p = __expf(v[j] - mnew);
            v[j] = tf32r(p);
            sl += p;
        }
        sl += __shfl_xor_sync(0xffffffffu, sl, 1);
        sl += __shfl_xor_sync(0xffffffffu, sl, 2);
        srun = srun * corr + sl;
        mrun = mnew;
#pragma unroll
        for (int q = 0; q < 4; q++)
            *(float4*)&sP[sr * AST + cg * 16 + q * 4] = *(float4*)&v[q * 4];
        if (cg == 0) sCr[sr] = corr;
        __syncthreads();

        // rescale O accumulators
#pragma unroll
        for (int mi = 0; mi < 2; mi++) {
            int r0 = warp_m * 32 + mi * 16 + g;
            float c0f = sCr[r0], c8f = sCr[r0 + 8];
#pragma unroll
            for (int nf = 0; nf < 2; nf++) {
                acc_o[mi][nf][0] *= c0f; acc_o[mi][nf][1] *= c0f;
                acc_o[mi][nf][2] *= c8f; acc_o[mi][nf][3] *= c8f;
            }
        }

        // O += P @ V
#pragma unroll
        for (int kf = 0; kf < 8; kf++) {
            const int co = kf * 8 + t;
            uint32_t a[2][4], b[2][2];
#pragma unroll
            for (int mi = 0; mi < 2; mi++) {
                int r = warp_m * 32 + mi * 16 + g;
                a[mi][0] = __float_as_uint(sP[r * AST + co]);
                a[mi][1] = __float_as_uint(sP[(r + 8) * AST + co]);
                a[mi][2] = __float_as_uint(sP[r * AST + co + 4]);
                a[mi][3] = __float_as_uint(sP[(r + 8) * AST + co + 4]);
            }
#pragma unroll
            for (int nf = 0; nf < 2; nf++) {
                int d0 = warp_n * 16 + nf * 8 + g;
                b[nf][0] = __float_as_uint(cV[(kf * 8 + t) * AST + d0]);
                b[nf][1] = __float_as_uint(cV[(kf * 8 + t + 4) * AST + d0]);
            }
#pragma unroll
            for (int mi = 0; mi < 2; mi++)
#pragma unroll
                for (int nf = 0; nf < 2; nf++)
                    mma_16x8x8(acc_o[mi][nf], a[mi], b[nf]);
        }
        __syncthreads();
    }
    CP_WAIT0();

    if (cg == 0) sCr[sr] = 1.f / srun;
    __syncthreads();
#pragma unroll
    for (int mi = 0; mi < 2; mi++) {
        int r0 = warp_m * 32 + mi * 16 + g;
        float i0 = sCr[r0], i8 = sCr[r0 + 8];
#pragma unroll
        for (int nf = 0; nf < 2; nf++) {
            int c0 = warp_n * 16 + nf * 8 + 2 * t;
            sP[r0 * AST + c0]           = acc_o[mi][nf][0] * i0;
            sP[r0 * AST + c0 + 1]       = acc_o[mi][nf][1] * i0;
            sP[(r0 + 8) * AST + c0]     = acc_o[mi][nf][2] * i8;
            sP[(r0 + 8) * AST + c0 + 1] = acc_o[mi][nf][3] * i8;
        }
    }
    __syncthreads();
#pragma unroll
    for (int i = 0; i < 4; i++) {
        int f = tid + i * 256;
        int r = f >> 4, c4 = (f & 15) * 4;
        *(float4*)(Ob + (long long)r * 64 + c4) = *(float4*)&sP[r * AST + c4];
    }
}

// ---------------- round x to tf32 (pre-pass) ----------------
__global__ __launch_bounds__(256) void round_kernel(const float* __restrict__ src,
                                                    float* __restrict__ dst, int n4)
{
    for (int i = blockIdx.x * 256 + threadIdx.x; i < n4; i += gridDim.x * 256) {
        float4 v = *(const float4*)(src + (long long)i * 4);
        v.x = tf32r(v.x); v.y = tf32r(v.y); v.z = tf32r(v.z); v.w = tf32r(v.w);
        *(float4*)(dst + (long long)i * 4) = v;
    }
}

// ---------------- weight transpose (+tf32 round) ----------------
__global__ void transpose_kernel(const float* __restrict__ src, float* __restrict__ dst,
                                 int R, int C)
{
    __shared__ float tbuf[32][33];
    int c0 = blockIdx.x * 32, r0 = blockIdx.y * 32;
    int x = threadIdx.x, y = threadIdx.y;
#pragma unroll
    for (int i = 0; i < 32; i += 8) tbuf[y + i][x] = src[(long long)(r0 + y + i) * C + c0 + x];
    __syncthreads();
#pragma unroll
    for (int i = 0; i < 32; i += 8)
        dst[(long long)(c0 + y + i) * R + r0 + x] = tf32r(tbuf[x][y + i]);
}

// ---------------- FFMA NN GEMM (W = Z @ A3V; outputs tf32-rounded) ----------------
__global__ __launch_bounds__(256) void gemm_nn(
    const float* __restrict__ A, const float* __restrict__ B,
    float* __restrict__ C, int Md, int Nd, int Kd,
    long long sA, long long sB, long long sC)
{
    A += (long long)blockIdx.z * sA;
    B += (long long)blockIdx.z * sB;
    C += (long long)blockIdx.z * sC;
    const int m0 = blockIdx.x * 128;
    const int n0 = blockIdx.y * 128;
    const int tid = threadIdx.x;
    const int tx = tid & 15, ty = tid >> 4;
    __shared__ float As[8][132];
    __shared__ float Bs[8][128];
    float acc[8][8];
#pragma unroll
    for (int i = 0; i < 8; i++)
#pragma unroll
        for (int j = 0; j < 8; j++) acc[i][j] = 0.f;
    const int ar = tid >> 1, ac = (tid & 1) * 4;
    const int bk = tid >> 5, bn = (tid & 31) * 4;
    const bool bok = (n0 + bn < Nd);
    for (int kk = 0; kk < Kd; kk += 8) {
        float4 av = *(const float4*)(A + (long long)(m0 + ar) * Kd + kk + ac);
        float4 bv = make_float4(0.f, 0.f, 0.f, 0.f);
        if (bok) bv = *(const float4*)(B + (long long)(kk + bk) * Nd + n0 + bn);
        As[ac + 0][ar] = av.x; As[ac + 1][ar] = av.y;
        As[ac + 2][ar] = av.z; As[ac + 3][ar] = av.w;
        *(float4*)&Bs[bk][bn] = bv;
        __syncthreads();
#pragma unroll
        for (int k = 0; k < 8; k++) {
            float a[8], b[8];
            *(float4*)&a[0] = *(const float4*)&As[k][ty * 8];
            *(float4*)&a[4] = *(const float4*)&As[k][ty * 8 + 4];
            *(float4*)&b[0] = *(const float4*)&Bs[k][tx * 8];
            *(float4*)&b[4] = *(const float4*)&Bs[k][tx * 8 + 4];
#pragma unroll
            for (int i = 0; i < 8; i++)
#pragma unroll
                for (int j = 0; j < 8; j++)
                    acc[i][j] = fmaf(a[i], b[j], acc[i][j]);
        }
        __syncthreads();
    }
#pragma unroll
    for (int i = 0; i < 8; i++) {
        int row = m0 + ty * 8 + i;
        if (row >= Md) continue;
#pragma unroll
        for (int jg = 0; jg < 8; jg += 4) {
            int col = n0 + tx * 8 + jg;
            if (col >= Nd) continue;
            float4 o = make_float4(tf32r(acc[i][jg]), tf32r(acc[i][jg + 1]),
                                   tf32r(acc[i][jg + 2]), tf32r(acc[i][jg + 3]));
            *(float4*)(C + (long long)row * Nd + col) = o;
        }
    }
}

// ---------------- landmark means (+tf32 round) ----------------
__global__ void landmark_kernel(const float* __restrict__ src, float* __restrict__ dst)
{
    int m = blockIdx.x, bh = blockIdx.y, d = threadIdx.x;
    const float* p = src + ((long long)bh * N_ + (long long)m * L_) * DH_ + d;
    float s = 0.f;
#pragma unroll
    for (int i = 0; i < L_; i++) s += p[i * DH_];
    dst[((long long)bh * M_ + m) * DH_ + d] = tf32r(s * (1.f / (float)L_));
}

__device__ __forceinline__ float warpMaxRed(float v) {
#pragma unroll
    for (int o = 16; o; o >>= 1) v = fmaxf(v, __shfl_xor_sync(0xffffffffu, v, o));
    return v;
}
__device__ __forceinline__ float warpSumRed(float v) {
#pragma unroll
    for (int o = 16; o; o >>= 1) v += __shfl_xor_sync(0xffffffffu, v, o);
    return v;
}

__global__ __launch_bounds__(256) void softmax_rows256(float* __restrict__ A)
{
    int warp = threadIdx.x >> 5, lane = threadIdx.x & 31;
    long long row = (long long)blockIdx.x * 8 + warp;
    float* p = A + row * 256;
    float4 v0 = *(float4*)(p + lane * 8);
    float4 v1 = *(float4*)(p + lane * 8 + 4);
    float mx = fmaxf(fmaxf(fmaxf(v0.x, v0.y), fmaxf(v0.z, v0.w)),
                     fmaxf(fmaxf(v1.x, v1.y), fmaxf(v1.z, v1.w)));
    mx = warpMaxRed(mx);
    v0.x = __expf(v0.x - mx); v0.y = __expf(v0.y - mx);
    v0.z = __expf(v0.z - mx); v0.w = __expf(v0.w - mx);
    v1.x = __expf(v1.x - mx); v1.y = __expf(v1.y - mx);
    v1.z = __expf(v1.z - mx); v1.w = __expf(v1.w - mx);
    float sm = v0.x + v0.y + v0.z + v0.w + v1.x + v1.y + v1.z + v1.w;
    sm = warpSumRed(sm);
    float inv = 1.f / sm;
    v0.x = tf32r(v0.x * inv); v0.y = tf32r(v0.y * inv);
    v0.z = tf32r(v0.z * inv); v0.w = tf32r(v0.w * inv);
    v1.x = tf32r(v1.x * inv); v1.y = tf32r(v1.y * inv);
    v1.z = tf32r(v1.z * inv); v1.w = tf32r(v1.w * inv);
    *(float4*)(p + lane * 8) = v0;
    *(float4*)(p + lane * 8 + 4) = v1;
}

// ---------------- pinv support ----------------
__global__ void init_max_kernel() { gMaxBits = 0; }

__global__ __launch_bounds__(256) void colmax_kernel(const float* __restrict__ A2)
{
    int bh = blockIdx.x, j = threadIdx.x;
    const float* p = A2 + ((long long)bh << 16) + j;
    float s = 0.f;
#pragma unroll 8
    for (int i = 0; i < 256; i++) s += p[i << 8];
    atomicMax(&gMaxBits, __float_as_int(s));
}

__global__ __launch_bounds__(256) void zinit_kernel(const float* __restrict__ A2,
                                                    float* __restrict__ Z,
                                                    float* __restrict__ ZT)
{
    int idx = blockIdx.x * 256 + threadIdx.x;
    float inv = 1.f / __int_as_float(gMaxBits);
    int bh = idx >> 16, r = idx & 65535, i = r >> 8, j = r & 255;
    Z[idx]  = tf32r(A2[(bh << 16) + (j << 8) + i] * inv);
    ZT[idx] = tf32r(A2[idx] * inv);
}

// ---------------- depthwise conv(k=33) + add + concat heads (+tf32 round) ----------
__global__ __launch_bounds__(256) void convcat_kernel(
    const float* __restrict__ V, const float* __restrict__ OH,
    const float* __restrict__ ker, float* __restrict__ CAT)
{
    int b = blockIdx.z, h = blockIdx.y, n0 = blockIdx.x * 64;
    int bh = b * H_ + h;
    __shared__ float sV[96][64];
    __shared__ float kw[33];
    int t = threadIdx.x;
    if (t < 33) kw[t] = ker[h * 33 + t];
    const float* Vb = V + (long long)bh * N_ * DH_;
    for (int idx = t; idx < 96 * 16; idx += 256) {
        int r = idx >> 4;
        int c4 = (idx & 15) * 4;
        int n = n0 - 16 + r;
        float4 val = make_float4(0.f, 0.f, 0.f, 0.f);
        if (n >= 0 && n < N_) val = *(const float4*)(Vb + (long long)n * DH_ + c4);
        *(float4*)&sV[r][c4] = val;
    }
    __syncthreads();
    int d = t & 63, nl0 = t >> 6;
#pragma unroll
    for (int ii = 0; ii < 16; ii++) {
        int nl = nl0 + ii * 4;
        float acc = 0.f;
#pragma unroll
        for (int tt = 0; tt < 33; tt++) acc = fmaf(sV[nl + tt][d], kw[tt], acc);
        int n = n0 + nl;
        float o = OH[((long long)bh * N_ + n) * DH_ + d] + acc;
        CAT[((long long)(b * N_ + n)) * 512 + h * 64 + d] = tf32r(o);
    }
}

// ---------------- host ----------------
extern "C" void kernel_launch(void* const* d_in, const int* in_sizes, int n_in,
                              void* d_out, int out_size)
{
    const float* x     = (const float*)d_in[0];
    const float* wqkv  = (const float*)d_in[1];
    const float* wout  = (const float*)d_in[2];
    const float* bout  = (const float*)d_in[3];
    const float* rker  = (const float*)d_in[4];
    float* out = (float*)d_out;

    cudaFuncSetAttribute(gemm_mma, cudaFuncAttributeMaxDynamicSharedMemorySize, DYN_SMEM);
    cudaFuncSetAttribute(gemm_mma_qkv, cudaFuncAttributeMaxDynamicSharedMemorySize, DYN_SMEM);
    cudaFuncSetAttribute(fused_attn_mma, cudaFuncAttributeMaxDynamicSharedMemorySize, DYN_ATTN);

    float *pQ, *pK, *pV, *pQL, *pKL, *pA2, *pZ, *pZT, *pZ2, *pZ2T, *pX;
    float *pT1, *pT2, *pA3V, *pW, *pOH, *pCAT, *pWqkvT, *pWoutT;
    cudaGetSymbolAddress((void**)&pQ,  gQ);
    cudaGetSymbolAddress((void**)&pK,  gK);
    cudaGetSymbolAddress((void**)&pV,  gV);
    cudaGetSymbolAddress((void**)&pQL, gQL);
    cudaGetSymbolAddress((void**)&pKL, gKL);
    cudaGetSymbolAddress((void**)&pA2, gA2);
    cudaGetSymbolAddress((void**)&pZ,  gZ);
    cudaGetSymbolAddress((void**)&pZT, gZT);
    cudaGetSymbolAddress((void**)&pZ2, gZ2);
    cudaGetSymbolAddress((void**)&pZ2T, gZ2T);
    cudaGetSymbolAddress((void**)&pX,  gX);
    cudaGetSymbolAddress((void**)&pT1, gT1);
    cudaGetSymbolAddress((void**)&pT2, gT2);
    cudaGetSymbolAddress((void**)&pA3V, gA3V);
    cudaGetSymbolAddress((void**)&pW,  gW);
    cudaGetSymbolAddress((void**)&pOH, gOH);
    cudaGetSymbolAddress((void**)&pCAT, gCAT);
    cudaGetSymbolAddress((void**)&pWqkvT, gWqkvT);
    cudaGetSymbolAddress((void**)&pWoutT, gWoutT);

    const long long MM = (long long)M_ * M_;
    const long long MD = (long long)M_ * DH_;
    const long long ND = (long long)N_ * DH_;

    // 0) tf32-round x into gCAT; transpose+round weights
    round_kernel<<<4096, 256>>>(x, pCAT, 4194304);
    transpose_kernel<<<dim3(48, 16), dim3(32, 8)>>>(wqkv, pWqkvT, 512, 1536);
    transpose_kernel<<<dim3(16, 16), dim3(32, 8)>>>(wout, pWoutT, 512, 512);
    // 1) qkv GEMM with scatter epilogue (outputs tf32-rounded)
    gemm_mma_qkv<<<dim3(256, 12), 256, DYN_SMEM>>>(pCAT, pWqkvT, pQ, pK, pV);
    // 2) landmarks
    landmark_kernel<<<dim3(M_, BH_), DH_>>>(pQ, pQL);
    landmark_kernel<<<dim3(M_, BH_), DH_>>>(pK, pKL);
    // 3) attn2 = softmax(QL @ KL^T)
    gemm_mma<<<dim3(2, 2, BH_), 256, DYN_SMEM>>>(pQL, pKL, pA2, nullptr, nullptr,
                                                 64, 256, 0, MD, MD, MM, 0,
                                                 1.f, 0.f, 0.f, 0.f, 0);
    softmax_rows256<<<1024, 256>>>(pA2);
    // 4) pinv init
    init_max_kernel<<<1, 1>>>();
    colmax_kernel<<<BH_, 256>>>(pA2);
    zinit_kernel<<<8192, 256>>>(pA2, pZ, pZT);
    // 5) Newton-Schulz iterations
    float *zin = pZ, *zinT = pZT, *zout = pZ2, *zoutT = pZ2T;
    for (int it = 0; it < 6; it++) {
        gemm_mma<<<dim3(2, 2, BH_), 256, DYN_SMEM>>>(pA2, zinT, pX, pT1, nullptr,
                                                     256, 256, 256, MM, MM, MM, MM,
                                                     1.f, 0.f, -1.f, 7.f, 1);
        gemm_mma<<<dim3(2, 2, BH_), 256, DYN_SMEM>>>(pX, pT1, nullptr, pT2, nullptr,
                                                     256, 256, 256, MM, MM, MM, MM,
                                                     0.f, 0.f, -1.f, 15.f, 1);
        gemm_mma<<<dim3(2, 2, BH_), 256, DYN_SMEM>>>(pX, pT2, nullptr, pT1, nullptr,
                                                     256, 256, 256, MM, MM, MM, MM,
                                                     0.f, 0.f, -1.f, 13.f, 1);
        gemm_mma<<<dim3(2, 2, BH_), 256, DYN_SMEM>>>(zin, pT1, zout, zoutT, nullptr,
                                                     256, 256, 256, MM, MM, MM, MM,
                                                     0.25f, 0.f, 0.25f, 0.f, 1);
        float* t;
        t = zin; zin = zout; zout = t;
        t = zinT; zinT = zoutT; zoutT = t;
    }
    // 6) A3V = softmax(QL @ K^T) @ V (tensor-core flash)
    fused_attn_mma<<<dim3(4, BH_), 256, DYN_ATTN>>>(pQL, pK, pV, pA3V,
                                                    N_ / 64, MD, ND, MD);
    // 7) W = Zfinal @ A3V (FFMA NN, outputs rounded)
    gemm_nn<<<dim3(2, 1, BH_), 256>>>(zin, pA3V, pW, 256, 64, 256, MM, MD, MD);
    // 8) OH = softmax(Q @ KL^T) @ W (tensor-core flash)
    fused_attn_mma<<<dim3(128, BH_), 256, DYN_ATTN>>>(pQ, pKL, pW, pOH,
                                                      M_ / 64, ND, MD, ND);
    // 9) conv + concat
    convcat_kernel<<<dim3(128, H_, B_), 256>>>(pV, pOH, rker, pCAT);
    // 10) out = CAT @ wout + bout
    gemm_mma<<<dim3(256, 4), 256, DYN_SMEM>>>(pCAT, pWoutT, out, nullptr, bout,
                                              512, 512, 0, 0, 0, 0, 0,
                                              1.f, 0.f, 0.f, 0.f, 0);
}